// round 2
// baseline (speedup 1.0000x reference)
#include <cuda_runtime.h>
#include <math.h>

// ---------------- problem constants ----------------
#define N3   405224   // 74^3

typedef unsigned long long ull;

// ---------------- f32x2 packed helpers ----------------
__device__ __forceinline__ ull pk(float lo, float hi) {
    ull r; asm("mov.b64 %0, {%1,%2};" : "=l"(r) : "f"(lo), "f"(hi)); return r;
}
__device__ __forceinline__ float2 unpk(ull p) {
    float2 f; asm("mov.b64 {%0,%1}, %2;" : "=f"(f.x), "=f"(f.y) : "l"(p)); return f;
}
__device__ __forceinline__ void fma2(ull& d, ull a, ull b, ull c) {
    asm("fma.rn.f32x2 %0, %1, %2, %3;" : "=l"(d) : "l"(a), "l"(b), "l"(c));
}

// ---------------- device scratch ----------------
__device__ float g_buf1[2 * 32 * 78 * 78 * 78];   // conv1 out / conv3 out
__device__ float g_buf2[2 * 32 * 76 * 76 * 76];   // conv2 out
__device__ float g_k[2 * 64 * N3];                // k, layout [b][d][j]
__device__ float g_v[2 * 64 * N3];                // v, layout [b][d][j]
__device__ float g_slots[1024];
__device__ float g_q[1024];                       // [b][i][d], scale folded in
__device__ float g_upd[1024];                     // [b][i][d] numerator accumulators
__device__ float g_rowsum[16];                    // [b][i]

// =====================================================================
// Conv3d 3x3x3 VALID, Cout=32, relu.  Tile: 4(D) x 8(H) x 8(W), 256 thr.
// thread = (cout, h-row); owns 4x8 outputs as 4x4 f32x2 pairs.
// fma.rn.f32x2 doubles fp32 FMA throughput (FFMA2 path).
// =====================================================================
template <int CIN>
__global__ __launch_bounds__(256)
void conv3d_kernel(const float* __restrict__ in, const float* __restrict__ wg,
                   const float* __restrict__ bias, float* __restrict__ out,
                   int Di) {
    const int Do = Di - 2;
    const int tid = threadIdx.x;
    const int b  = blockIdx.z;
    const int nW = (Do + 7) >> 3;
    const int h0 = (blockIdx.x / nW) * 8;
    const int w0 = (blockIdx.x % nW) * 8;
    const int d0 = blockIdx.y * 4;

    extern __shared__ float smem[];
    float* ws    = smem;                 // CIN*27*32, layout [ci*27+t][cout]
    float* patch = smem + CIN * 27 * 32; // CIN*600 (>=8192 for out staging)

    // load + transpose weights
    const int WTOT = 32 * CIN * 27;
    for (int idx = tid; idx < WTOT; idx += 256) {
        int co = idx / (CIN * 27);
        int r  = idx - co * (CIN * 27);
        ws[r * 32 + co] = wg[idx];
    }
    // load input patch CIN x 6 x 10 x 10 (zero-fill OOB)
    for (int idx = tid; idx < CIN * 600; idx += 256) {
        int ci = idx / 600;
        int r  = idx - ci * 600;
        int dd = r / 100;  int r2 = r - dd * 100;
        int hh = r2 / 10;  int ww = r2 - hh * 10;
        int gd = d0 + dd, gh = h0 + hh, gw = w0 + ww;
        float val = 0.f;
        if (gd < Di && gh < Di && gw < Di)
            val = in[(((b * CIN + ci) * Di + gd) * Di + gh) * Di + gw];
        patch[idx] = val;
    }
    __syncthreads();

    const int cout = tid >> 3;
    const int hg   = tid & 7;
    const float bv = bias[cout];

    ull acc[4][4];
#pragma unroll
    for (int i = 0; i < 4; i++)
#pragma unroll
        for (int j = 0; j < 4; j++) acc[i][j] = 0ull;

    for (int ci = 0; ci < CIN; ci++) {
        ull wp[27];
#pragma unroll
        for (int t = 0; t < 27; t++) {
            float wv = ws[(ci * 27 + t) * 32 + cout];
            wp[t] = pk(wv, wv);
        }
        const float* pbase = patch + ci * 600;
#pragma unroll
        for (int kh = 0; kh < 3; kh++) {
#pragma unroll
            for (int dd = 0; dd < 6; dd++) {
                const ull* rp = (const ull*)(pbase + dd * 100 + (hg + kh) * 10);
                ull P[5];
#pragma unroll
                for (int j = 0; j < 5; j++) P[j] = rp[j];
                ull Q[4];
#pragma unroll
                for (int j = 0; j < 4; j++) {
                    float2 a = unpk(P[j]);
                    float2 bq = unpk(P[j + 1]);
                    Q[j] = pk(a.y, bq.x);
                }
#pragma unroll
                for (int kd = 0; kd < 3; kd++) {
                    const int dlo = dd - kd;
                    if (dlo >= 0 && dlo < 4) {
                        const int tb = kd * 9 + kh * 3;
#pragma unroll
                        for (int j = 0; j < 4; j++) {
                            fma2(acc[dlo][j], P[j],     wp[tb],     acc[dlo][j]);
                            fma2(acc[dlo][j], Q[j],     wp[tb + 1], acc[dlo][j]);
                            fma2(acc[dlo][j], P[j + 1], wp[tb + 2], acc[dlo][j]);
                        }
                    }
                }
            }
        }
    }
    __syncthreads();   // done with patch
    // stage outputs (relu + bias) for coalesced store
#pragma unroll
    for (int dd = 0; dd < 4; dd++)
#pragma unroll
        for (int j = 0; j < 4; j++) {
            float2 p = unpk(acc[dd][j]);
            float v0 = p.x + bv, v1 = p.y + bv;
            patch[cout * 256 + dd * 64 + hg * 8 + 2 * j]     = v0 > 0.f ? v0 : 0.f;
            patch[cout * 256 + dd * 64 + hg * 8 + 2 * j + 1] = v1 > 0.f ? v1 : 0.f;
        }
    __syncthreads();
    const int DoDo = Do * Do;
    for (int idx = tid; idx < 8192; idx += 256) {
        int co = idx >> 8;
        int r  = idx & 255;
        int dd = r >> 6;
        int hh = (r >> 3) & 7;
        int w  = r & 7;
        int od = d0 + dd, oh = h0 + hh, ow = w0 + w;
        if (od < Do && oh < Do && ow < Do)
            out[((b * 32 + co) * Do + od) * DoDo + oh * Do + ow] = patch[idx];
    }
}

// =====================================================================
// feature LN + k/v projection. x: [b][c][j] (conv3 out), k/v out d-major.
// f32x2 dual-lane dot products, horizontal add at the end.
// =====================================================================
__global__ __launch_bounds__(256)
void lnkv_kernel(const float* __restrict__ x, const float* __restrict__ lg,
                 const float* __restrict__ lb, const float* __restrict__ kw,
                 const float* __restrict__ vw) {
    __shared__ float kws[2048], vws[2048], gs[32], bs[32];
    const int tid = threadIdx.x;
    for (int i = tid; i < 2048; i += 256) { kws[i] = kw[i]; vws[i] = vw[i]; }
    if (tid < 32) { gs[tid] = lg[tid]; bs[tid] = lb[tid]; }
    __syncthreads();
    const int b = blockIdx.y;
    const int j = blockIdx.x * 256 + tid;
    if (j >= N3) return;
    float xv[32];
    float s = 0.f;
#pragma unroll
    for (int c = 0; c < 32; c++) { xv[c] = x[(b * 32 + c) * N3 + j]; s += xv[c]; }
    const float m = s * (1.f / 32.f);
    float vs = 0.f;
#pragma unroll
    for (int c = 0; c < 32; c++) { float d = xv[c] - m; vs += d * d; }
    const float inv = rsqrtf(vs * (1.f / 32.f) + 1e-5f);
    ull xp[16];
#pragma unroll
    for (int c2 = 0; c2 < 16; c2++) {
        float a0 = (xv[2 * c2] - m) * inv * gs[2 * c2] + bs[2 * c2];
        float a1 = (xv[2 * c2 + 1] - m) * inv * gs[2 * c2 + 1] + bs[2 * c2 + 1];
        xp[c2] = pk(a0, a1);
    }
#pragma unroll 4
    for (int d = 0; d < 64; d++) {
        const ull* k8 = (const ull*)(kws + d * 32);
        const ull* v8 = (const ull*)(vws + d * 32);
        ull ka = 0ull, va = 0ull;
#pragma unroll
        for (int c2 = 0; c2 < 16; c2++) {
            fma2(ka, xp[c2], k8[c2], ka);
            fma2(va, xp[c2], v8[c2], va);
        }
        float2 kp = unpk(ka), vp = unpk(va);
        g_k[(b * 64 + d) * N3 + j] = kp.x + kp.y;
        g_v[(b * 64 + d) * N3 + j] = vp.x + vp.y;
    }
}

// =====================================================================
// q = LN(slots) @ q_w^T * SD^-0.5 ; also zeroes iteration accumulators.
// =====================================================================
__global__ __launch_bounds__(256)
void q_kernel(const float* __restrict__ slots, const float* __restrict__ lg,
              const float* __restrict__ lb, const float* __restrict__ qw) {
    __shared__ float s[1024], qws[4096], gs[64], bs[64], mm[16], iv[16];
    const int tid = threadIdx.x;
    for (int i = tid; i < 1024; i += 256) { s[i] = slots[i]; g_upd[i] = 0.f; }
    for (int i = tid; i < 4096; i += 256) qws[i] = qw[i];
    if (tid < 64) { gs[tid] = lg[tid]; bs[tid] = lb[tid]; }
    if (tid < 16) g_rowsum[tid] = 0.f;
    __syncthreads();
    if (tid < 16) {
        float sum = 0.f;
        for (int d = 0; d < 64; d++) sum += s[tid * 64 + d];
        float m = sum * (1.f / 64.f);
        float vs = 0.f;
        for (int d = 0; d < 64; d++) { float t = s[tid * 64 + d] - m; vs += t * t; }
        mm[tid] = m;
        iv[tid] = rsqrtf(vs * (1.f / 64.f) + 1e-5f);
    }
    __syncthreads();
    for (int k = 0; k < 4; k++) {
        int o = k * 256 + tid;
        int r = o >> 6, d = o & 63;
        float m = mm[r], inv = iv[r];
        float acc = 0.f;
#pragma unroll
        for (int c = 0; c < 64; c++)
            acc += ((s[r * 64 + c] - m) * inv * gs[c] + bs[c]) * qws[d * 64 + c];
        g_q[o] = acc * 0.125f;   // 64^-0.5
    }
}

// =====================================================================
// fused attention iteration: dots -> softmax over 8 slots -> (+eps)
// -> accumulate rowsum and Sum_j a*v  (normalization folded out).
// =====================================================================
__global__ __launch_bounds__(256)
void attn_kernel(float* __restrict__ attn_out) {
    extern __shared__ float sm[];
    float* qs = sm;             // 512
    float* as = sm + 512;       // 8 * 256
    float* vs = sm + 2560;      // 64 * 257 (padded)
    const int tid  = threadIdx.x;
    const int b    = blockIdx.y;
    const int dd   = tid & 63;
    const int ib   = tid >> 6;          // 0..3 ; pairs (ib,dd),(ib+4,dd)
    const int wid  = tid >> 5;
    const int lane = tid & 31;
    for (int i = tid; i < 512; i += 256) qs[i] = g_q[b * 512 + i];

    float acc0 = 0.f, acc1 = 0.f, rs = 0.f;
    const int nch = (N3 + 255) >> 8;
    for (int c = blockIdx.x; c < nch; c += gridDim.x) {
        const int j0 = c << 8;
        const int j  = j0 + tid;
        __syncthreads();
        // ---- phase 1: dots + softmax over slots ----
        float a[8];
        if (j < N3) {
            float dots[8];
#pragma unroll
            for (int i = 0; i < 8; i++) dots[i] = 0.f;
#pragma unroll 16
            for (int d = 0; d < 64; d++) {
                float kv = g_k[(b * 64 + d) * N3 + j];
#pragma unroll
                for (int i = 0; i < 8; i++) dots[i] += qs[i * 64 + d] * kv;
            }
            float mx = dots[0];
#pragma unroll
            for (int i = 1; i < 8; i++) mx = fmaxf(mx, dots[i]);
            float ssum = 0.f;
#pragma unroll
            for (int i = 0; i < 8; i++) { a[i] = expf(dots[i] - mx); ssum += a[i]; }
            const float rinv = 1.f / ssum;
#pragma unroll
            for (int i = 0; i < 8; i++) a[i] = a[i] * rinv + 1e-8f;
            if (attn_out) {
#pragma unroll
                for (int i = 0; i < 8; i++)
                    attn_out[(b * 8 + i) * N3 + j] = a[i];
            }
        } else {
#pragma unroll
            for (int i = 0; i < 8; i++) a[i] = 0.f;
        }
#pragma unroll
        for (int i = 0; i < 8; i++) as[i * 256 + tid] = a[i];
        // cooperative v chunk load
        for (int idx = tid; idx < 64 * 256; idx += 256) {
            int d  = idx >> 8, jj = idx & 255;
            int jg = j0 + jj;
            vs[d * 257 + jj] = (jg < N3) ? g_v[(b * 64 + d) * N3 + jg] : 0.f;
        }
        __syncthreads();
        // ---- rowsum: warp w reduces slot-row w ----
        {
            float p = 0.f;
#pragma unroll
            for (int k = 0; k < 8; k++) p += as[wid * 256 + lane + k * 32];
#pragma unroll
            for (int off = 16; off; off >>= 1) p += __shfl_xor_sync(0xffffffffu, p, off);
            rs += p;
        }
        // ---- phase 2: update GEMM chunk ----
        const float* ap0 = as + ib * 256;
        const float* ap1 = as + (ib + 4) * 256;
        const float* vp  = vs + dd * 257;
#pragma unroll 8
        for (int jj = 0; jj < 256; jj++) {
            float vv = vp[jj];
            acc0 += ap0[jj] * vv;
            acc1 += ap1[jj] * vv;
        }
    }
    atomicAdd(&g_upd[(b * 8 + ib) * 64 + dd], acc0);
    atomicAdd(&g_upd[(b * 8 + ib + 4) * 64 + dd], acc1);
    if (lane == 0) atomicAdd(&g_rowsum[b * 8 + wid], rs);
}

// =====================================================================
// GRU cell + LN + MLP residual over the 16 slot rows. One block.
// =====================================================================
__global__ __launch_bounds__(512)
void gru_kernel(const float* __restrict__ slots_prev,
                const float* __restrict__ wih, const float* __restrict__ whh,
                const float* __restrict__ bih, const float* __restrict__ bhh,
                const float* __restrict__ lng, const float* __restrict__ lnb,
                const float* __restrict__ w1, const float* __restrict__ rb1,
                const float* __restrict__ w2, const float* __restrict__ rb2,
                float* __restrict__ slots_final) {
    __shared__ float S[9216];
    float* u  = S;           // 1024
    float* h  = S + 1024;    // 1024
    float* xg = S + 2048;    // 3072
    float* hg = S + 5120;    // 3072
    float* nh = S + 8192;    // 1024
    float* normed = S + 2048;  // reuse xg
    float* t1     = S + 5120;  // reuse hg
    const int tid = threadIdx.x;

    for (int k = 0; k < 2; k++) {
        int idx = k * 512 + tid;
        int r = idx >> 6;
        u[idx] = g_upd[idx] / g_rowsum[r];
        h[idx] = slots_prev[idx];
    }
    __syncthreads();
    for (int k = 0; k < 6; k++) {
        int p = k * 512 + tid;
        int r = p / 192, c = p - r * 192;
        float xa = bih[c], ha = bhh[c];
        const float* wr = wih + c * 64;
        const float* hr = whh + c * 64;
#pragma unroll 16
        for (int d = 0; d < 64; d++) {
            xa += u[r * 64 + d] * wr[d];
            ha += h[r * 64 + d] * hr[d];
        }
        xg[p] = xa; hg[p] = ha;
    }
    __syncthreads();
    for (int k = 0; k < 2; k++) {
        int idx = k * 512 + tid;
        int r = idx >> 6, d = idx & 63;
        float rg = 1.f / (1.f + expf(-(xg[r * 192 + d] + hg[r * 192 + d])));
        float z  = 1.f / (1.f + expf(-(xg[r * 192 + 64 + d] + hg[r * 192 + 64 + d])));
        float n  = tanhf(xg[r * 192 + 128 + d] + rg * hg[r * 192 + 128 + d]);
        nh[idx] = (1.f - z) * n + z * h[idx];
    }
    __syncthreads();
    {   // LN per row, warp w <-> row w
        const int w = tid >> 5, lane = tid & 31;
        float e0 = nh[w * 64 + lane], e1 = nh[w * 64 + 32 + lane];
        float s = e0 + e1;
#pragma unroll
        for (int off = 16; off; off >>= 1) s += __shfl_xor_sync(0xffffffffu, s, off);
        float m = s * (1.f / 64.f);
        float d0 = e0 - m, d1 = e1 - m;
        float vq = d0 * d0 + d1 * d1;
#pragma unroll
        for (int off = 16; off; off >>= 1) vq += __shfl_xor_sync(0xffffffffu, vq, off);
        float inv = rsqrtf(vq * (1.f / 64.f) + 1e-5f);
        normed[w * 64 + lane]      = d0 * inv * lng[lane] + lnb[lane];
        normed[w * 64 + 32 + lane] = d1 * inv * lng[32 + lane] + lnb[32 + lane];
    }
    __syncthreads();
    for (int k = 0; k < 4; k++) {
        int p = k * 512 + tid;
        int r = p >> 7, c = p & 127;
        float acc = rb1[c];
        const float* wr = w1 + c * 64;
#pragma unroll 16
        for (int d = 0; d < 64; d++) acc += normed[r * 64 + d] * wr[d];
        t1[p] = fmaxf(acc, 0.f);
    }
    __syncthreads();
    for (int k = 0; k < 2; k++) {
        int idx = k * 512 + tid;
        int r = idx >> 6, d = idx & 63;
        float acc = rb2[d];
        const float* wr = w2 + d * 128;
#pragma unroll 16
        for (int c = 0; c < 128; c++) acc += t1[r * 128 + c] * wr[c];
        float val = nh[idx] + acc;
        g_slots[idx] = val;
        if (slots_final) slots_final[idx] = val;
    }
}

// =====================================================================
// host driver
// =====================================================================
extern "C" void kernel_launch(void* const* d_in, const int* in_sizes, int n_in,
                              void* d_out, int out_size) {
    (void)in_sizes; (void)n_in; (void)out_size;
    const float* p_slots = (const float*)d_in[0];
    const float* p_oin   = (const float*)d_in[1];
    const float* w1  = (const float*)d_in[2];
    const float* b1  = (const float*)d_in[3];
    const float* w2  = (const float*)d_in[4];
    const float* b2  = (const float*)d_in[5];
    const float* w3  = (const float*)d_in[6];
    const float* b3  = (const float*)d_in[7];
    const float* kw  = (const float*)d_in[8];
    const float* vw  = (const float*)d_in[9];
    const float* qlg = (const float*)d_in[10];
    const float* qlb = (const float*)d_in[11];
    const float* qw  = (const float*)d_in[12];
    const float* gwih = (const float*)d_in[13];
    const float* gwhh = (const float*)d_in[14];
    const float* gbih = (const float*)d_in[15];
    const float* gbhh = (const float*)d_in[16];
    const float* rlg = (const float*)d_in[17];
    const float* rlb = (const float*)d_in[18];
    const float* rw1 = (const float*)d_in[19];
    const float* rb1 = (const float*)d_in[20];
    const float* rw2 = (const float*)d_in[21];
    const float* rb2 = (const float*)d_in[22];
    const float* flg = (const float*)d_in[23];
    const float* flb = (const float*)d_in[24];
    float* out = (float*)d_out;

    const size_t smem32 = (size_t)(32 * 27 * 32 + 32 * 600) * sizeof(float);
    const size_t smem4  = (size_t)(4 * 27 * 32 + 8192) * sizeof(float);
    const size_t smemA  = (size_t)(512 + 2048 + 64 * 257) * sizeof(float);
    cudaFuncSetAttribute(conv3d_kernel<32>, cudaFuncAttributeMaxDynamicSharedMemorySize, (int)smem32);
    cudaFuncSetAttribute(conv3d_kernel<4>,  cudaFuncAttributeMaxDynamicSharedMemorySize, (int)smem4);
    cudaFuncSetAttribute(attn_kernel,       cudaFuncAttributeMaxDynamicSharedMemorySize, (int)smemA);

    float *buf1, *buf2, *slots_g;
    cudaGetSymbolAddress((void**)&buf1, g_buf1);
    cudaGetSymbolAddress((void**)&buf2, g_buf2);
    cudaGetSymbolAddress((void**)&slots_g, g_slots);

    // conv1: 80 -> 78
    conv3d_kernel<4><<<dim3(10 * 10, 20, 2), 256, smem4>>>(p_oin, w1, b1, buf1, 80);
    // conv2: 78 -> 76
    conv3d_kernel<32><<<dim3(10 * 10, 19, 2), 256, smem32>>>(buf1, w2, b2, buf2, 78);
    // conv3: 76 -> 74 (into buf1)
    conv3d_kernel<32><<<dim3(10 * 10, 19, 2), 256, smem32>>>(buf2, w3, b3, buf1, 76);
    // feature LN + k/v projection
    lnkv_kernel<<<dim3((N3 + 255) / 256, 2), 256>>>(buf1, flg, flb, kw, vw);

    for (int it = 0; it < 3; it++) {
        const float* sp = (it == 0) ? p_slots : slots_g;
        q_kernel<<<1, 256>>>(sp, qlg, qlb, qw);
        attn_kernel<<<dim3(222, 2), 256, smemA>>>((it == 2) ? (out + 1024) : (float*)0);
        gru_kernel<<<1, 512>>>(sp, gwih, gwhh, gbih, gbhh, rlg, rlb,
                               rw1, rb1, rw2, rb2, (it == 2) ? out : (float*)0);
    }
}

// round 5
// speedup vs baseline: 1.0991x; 1.0991x over previous
#include <cuda_runtime.h>
#include <cuda_bf16.h>
#include <math.h>
#include <stdint.h>

// ---------------- problem constants ----------------
#define N3   405224   // 74^3

typedef unsigned long long ull;

// ---------------- f32x2 packed helpers (lnkv) ----------------
__device__ __forceinline__ ull pk(float lo, float hi) {
    ull r; asm("mov.b64 %0, {%1,%2};" : "=l"(r) : "f"(lo), "f"(hi)); return r;
}
__device__ __forceinline__ float2 unpk(ull p) {
    float2 f; asm("mov.b64 {%0,%1}, %2;" : "=f"(f.x), "=f"(f.y) : "l"(p)); return f;
}
__device__ __forceinline__ void fma2(ull& d, ull a, ull b, ull c) {
    asm("fma.rn.f32x2 %0, %1, %2, %3;" : "=l"(d) : "l"(a), "l"(b), "l"(c));
}

// ---------------- device scratch ----------------
__device__ float g_buf1[2 * 32 * 78 * 78 * 78];   // conv1 out / conv3 out
__device__ float g_buf2[2 * 32 * 76 * 76 * 76];   // conv2 out
__device__ float g_k[2 * 64 * N3];
__device__ float g_v[2 * 64 * N3];
__device__ float g_slots[1024];
__device__ float g_q[1024];
__device__ float g_upd[1024];
__device__ float g_rowsum[16];
__device__ __nv_bfloat16 g_B2p[27 * 32 * 64];     // [tap][cout][hi32|lo32]
__device__ __nv_bfloat16 g_B3p[27 * 32 * 64];

// =====================================================================
// Weight prep: w[cout][cin][27] fp32 -> [tap][cout][hi(32)|lo(32)] bf16
// =====================================================================
__global__ void prepB_kernel(const float* __restrict__ w, __nv_bfloat16* __restrict__ Bg) {
    int idx = blockIdx.x * 256 + threadIdx.x;   // 0..27647
    if (idx >= 27648) return;
    int t = idx >> 10;
    int r = idx & 1023;
    int n = r >> 5;
    int ci = r & 31;
    float x = w[(n * 32 + ci) * 27 + t];
    __nv_bfloat16 hi = __float2bfloat16(x);
    float rem = x - __bfloat162float(hi);
    __nv_bfloat16 lo = __float2bfloat16(rem);
    Bg[(t * 32 + n) * 64 + ci] = hi;
    Bg[(t * 32 + n) * 64 + 32 + ci] = lo;
}

// =====================================================================
// mma.sync bf16 split-2 implicit-GEMM conv3d 3x3x3 VALID, 32ci->32co, relu.
// Persistent grid; CTA tile = 256 tokens (4d x 8h x 8w) x 32 cout.
// 8 warps x (32 tokens x 32 cout) each. fp32 accum in registers.
// smem: B (all 27 taps, padded rows) + patch (600 x [hi32|lo32], padded).
// =====================================================================
#define BROW_W 36                          // words per padded B row
#define B_BYTES (27 * 32 * BROW_W * 4)     // 124416
#define PROW_W 36                          // words per padded patch row
#define P_OFF  B_BYTES
#define P_BYTES (600 * PROW_W * 4)         // 86400
#define SMEM_MMA (P_OFF + P_BYTES)         // 210816

#define MMA_BF16(d, a, b)                                                  \
    asm volatile("mma.sync.aligned.m16n8k16.row.col.f32.bf16.bf16.f32 "    \
                 "{%0,%1,%2,%3}, {%4,%5,%6,%7}, {%8,%9}, {%0,%1,%2,%3};"   \
                 : "+f"(d[0]), "+f"(d[1]), "+f"(d[2]), "+f"(d[3])          \
                 : "r"(a[0]), "r"(a[1]), "r"(a[2]), "r"(a[3]),             \
                   "r"(b[0]), "r"(b[1]))

__global__ __launch_bounds__(256)
void conv_mma_kernel(const float* __restrict__ in, const __nv_bfloat16* __restrict__ Bg,
                     const float* __restrict__ bias, float* __restrict__ out, int Di) {
    const int Do = Di - 2;
    extern __shared__ char smem[];
    __shared__ float s_bias[32];
    const int tid  = threadIdx.x;
    const int wid  = tid >> 5;
    const int lane = tid & 31;
    const int grp  = lane >> 2;       // 0..7
    const int tig  = lane & 3;        // 0..3

    // copy B into smem with row padding (32 -> 36 words)
    {
        const uint32_t* src = (const uint32_t*)Bg;
        uint32_t* dst = (uint32_t*)smem;
        for (int i = tid; i < 27648; i += 256) {
            int row = i >> 5, w = i & 31;
            dst[row * BROW_W + w] = src[i];
        }
    }
    if (tid < 32) s_bias[tid] = bias[tid];
    __syncthreads();

    // per-thread token -> patch-row bases (2 mtiles x 2 row-halves)
    const int wbase = wid * 32;
    int srow[2][2];
    int tok[2][2];
#pragma unroll
    for (int mt = 0; mt < 2; mt++)
#pragma unroll
        for (int hf = 0; hf < 2; hf++) {
            int t = wbase + mt * 16 + grp + hf * 8;
            tok[mt][hf] = t;
            int d = t >> 6, h = (t >> 3) & 7, w = t & 7;
            srow[mt][hf] = d * 100 + h * 10 + w;
        }

    const int nd = (Do + 3) >> 2, nhw = (Do + 7) >> 3;   // 19, 10
    const int ntb = nd * nhw * nhw;
    const int DiDi = Di * Di, DoDo = Do * Do;
    char* patch = smem + P_OFF;

    for (int ti = blockIdx.x; ti < 2 * ntb; ti += gridDim.x) {
        const int b = ti / ntb;
        int r = ti - b * ntb;
        const int td = r / (nhw * nhw); r -= td * (nhw * nhw);
        const int th = r / nhw, tw = r - (r / nhw) * nhw;
        const int d0 = td * 4, h0 = th * 8, w0 = tw * 8;

        __syncthreads();   // previous tile's reads done
        // ---- patch fill: 600 spatial rows x 32 ci, hi|lo bf16 ----
        for (int ci = 0; ci < 32; ci++) {
            const float* src = in + (size_t)(b * 32 + ci) * Di * DiDi;
            for (int s = tid; s < 600; s += 256) {
                int pd = s / 100; int r2 = s - pd * 100;
                int ph = r2 / 10; int pw = r2 - ph * 10;
                int gd = d0 + pd, gh = h0 + ph, gw = w0 + pw;
                float x = 0.f;
                if (gd < Di && gh < Di && gw < Di) x = src[(gd * Di + gh) * Di + gw];
                __nv_bfloat16 hi = __float2bfloat16(x);
                float rem = x - __bfloat162float(hi);
                __nv_bfloat16 lo = __float2bfloat16(rem);
                *(__nv_bfloat16*)(patch + s * (PROW_W * 4) + ci * 2) = hi;
                *(__nv_bfloat16*)(patch + s * (PROW_W * 4) + 64 + ci * 2) = lo;
            }
        }
        __syncthreads();

        float acc[2][4][4];
#pragma unroll
        for (int mt = 0; mt < 2; mt++)
#pragma unroll
            for (int nt = 0; nt < 4; nt++)
#pragma unroll
                for (int q = 0; q < 4; q++) acc[mt][nt][q] = 0.f;

#pragma unroll 1
        for (int t = 0; t < 27; t++) {
            const int kd = t / 9; const int r9 = t - kd * 9;
            const int kh = r9 / 3; const int kw = r9 - kh * 3;
            const int toff = kd * 100 + kh * 10 + kw;
            const char* brow = smem + (size_t)t * 32 * (BROW_W * 4);
#pragma unroll
            for (int ks = 0; ks < 2; ks++) {
                // A fragments: [mt][split][4]
                uint32_t af[2][2][4];
#pragma unroll
                for (int mt = 0; mt < 2; mt++) {
                    const char* p0 = patch + (size_t)(srow[mt][0] + toff) * (PROW_W * 4) + ks * 32 + tig * 4;
                    const char* p1 = patch + (size_t)(srow[mt][1] + toff) * (PROW_W * 4) + ks * 32 + tig * 4;
#pragma unroll
                    for (int sp = 0; sp < 2; sp++) {
                        af[mt][sp][0] = *(const uint32_t*)(p0 + sp * 64);
                        af[mt][sp][1] = *(const uint32_t*)(p1 + sp * 64);
                        af[mt][sp][2] = *(const uint32_t*)(p0 + sp * 64 + 16);
                        af[mt][sp][3] = *(const uint32_t*)(p1 + sp * 64 + 16);
                    }
                }
                // B fragments: [nt][split][2]
                uint32_t bf[4][2][2];
#pragma unroll
                for (int nt = 0; nt < 4; nt++) {
                    const char* pb = brow + (size_t)(nt * 8 + grp) * (BROW_W * 4) + ks * 32 + tig * 4;
#pragma unroll
                    for (int sp = 0; sp < 2; sp++) {
                        bf[nt][sp][0] = *(const uint32_t*)(pb + sp * 64);
                        bf[nt][sp][1] = *(const uint32_t*)(pb + sp * 64 + 16);
                    }
                }
#pragma unroll
                for (int mt = 0; mt < 2; mt++)
#pragma unroll
                    for (int nt = 0; nt < 4; nt++) {
                        MMA_BF16(acc[mt][nt], af[mt][0], bf[nt][0]);   // hi*hi
                        MMA_BF16(acc[mt][nt], af[mt][1], bf[nt][0]);   // lo*hi
                        MMA_BF16(acc[mt][nt], af[mt][0], bf[nt][1]);   // hi*lo
                    }
            }
        }

        // ---- epilogue: bias + relu + predicated store ----
#pragma unroll
        for (int mt = 0; mt < 2; mt++)
#pragma unroll
            for (int nt = 0; nt < 4; nt++)
#pragma unroll
                for (int q = 0; q < 4; q++) {
                    int t = tok[mt][q >> 1];
                    int c = nt * 8 + tig * 2 + (q & 1);
                    int dd = t >> 6, hh = (t >> 3) & 7, ww = t & 7;
                    int od = d0 + dd, oh = h0 + hh, ow = w0 + ww;
                    if (od < Do && oh < Do && ow < Do) {
                        float v = acc[mt][nt][q] + s_bias[c];
                        out[(((size_t)(b * 32 + c) * Do + od) * Do + oh) * Do + ow] =
                            v > 0.f ? v : 0.f;
                    }
                }
    }
}

// =====================================================================
// Scalar conv for conv1 (CIN=4).
// =====================================================================
template <int CIN>
__global__ __launch_bounds__(256)
void conv3d_kernel(const float* __restrict__ in, const float* __restrict__ wg,
                   const float* __restrict__ bias, float* __restrict__ out,
                   int Di) {
    const int Do = Di - 2;
    const int tid = threadIdx.x;
    const int b  = blockIdx.z;
    const int nW = (Do + 7) >> 3;
    const int h0 = (blockIdx.x / nW) * 8;
    const int w0 = (blockIdx.x % nW) * 8;
    const int d0 = blockIdx.y * 4;

    extern __shared__ float smemf[];
    float* ws    = smemf;
    float* patch = smemf + CIN * 27 * 32;

    const int WTOT = 32 * CIN * 27;
    for (int idx = tid; idx < WTOT; idx += 256) {
        int co = idx / (CIN * 27);
        int r  = idx - co * (CIN * 27);
        ws[r * 32 + co] = wg[idx];
    }
    for (int idx = tid; idx < CIN * 600; idx += 256) {
        int ci = idx / 600;
        int r  = idx - ci * 600;
        int dd = r / 100;  int r2 = r - dd * 100;
        int hh = r2 / 10;  int ww = r2 - hh * 10;
        int gd = d0 + dd, gh = h0 + hh, gw = w0 + ww;
        float val = 0.f;
        if (gd < Di && gh < Di && gw < Di)
            val = in[(((b * CIN + ci) * Di + gd) * Di + gh) * Di + gw];
        patch[idx] = val;
    }
    __syncthreads();

    const int cout = tid >> 3;
    const int hg   = tid & 7;
    const float bv = bias[cout];

    float acc[4][8];
#pragma unroll
    for (int i = 0; i < 4; i++)
#pragma unroll
        for (int j = 0; j < 8; j++) acc[i][j] = 0.f;

    for (int ci = 0; ci < CIN; ci++) {
        float wr[27];
#pragma unroll
        for (int t = 0; t < 27; t++) wr[t] = ws[(ci * 27 + t) * 32 + cout];
        const float* pbase = patch + ci * 600;
#pragma unroll
        for (int kh = 0; kh < 3; kh++) {
            const float* rowb = pbase + (hg + kh) * 10;
#pragma unroll
            for (int dd = 0; dd < 6; dd++) {
                float row[10];
                const float2* rp = (const float2*)(rowb + dd * 100);
#pragma unroll
                for (int j = 0; j < 5; j++) ((float2*)row)[j] = rp[j];
#pragma unroll
                for (int kd = 0; kd < 3; kd++) {
                    const int dlo = dd - kd;
                    if (dlo >= 0 && dlo < 4) {
#pragma unroll
                        for (int kw = 0; kw < 3; kw++) {
                            float wv = wr[kd * 9 + kh * 3 + kw];
#pragma unroll
                            for (int w = 0; w < 8; w++)
                                acc[dlo][w] += wv * row[w + kw];
                        }
                    }
                }
            }
        }
    }
    __syncthreads();
#pragma unroll
    for (int dd = 0; dd < 4; dd++)
#pragma unroll
        for (int w = 0; w < 8; w++) {
            float v = acc[dd][w] + bv;
            patch[cout * 256 + dd * 64 + hg * 8 + w] = v > 0.f ? v : 0.f;
        }
    __syncthreads();
    const int DoDo = Do * Do;
    for (int idx = tid; idx < 8192; idx += 256) {
        int co = idx >> 8;
        int r  = idx & 255;
        int dd = r >> 6;
        int hh = (r >> 3) & 7;
        int w  = r & 7;
        int od = d0 + dd, oh = h0 + hh, ow = w0 + w;
        if (od < Do && oh < Do && ow < Do)
            out[((b * 32 + co) * Do + od) * DoDo + oh * Do + ow] = patch[idx];
    }
}

// =====================================================================
// feature LN + k/v projection
// =====================================================================
__global__ __launch_bounds__(256)
void lnkv_kernel(const float* __restrict__ x, const float* __restrict__ lg,
                 const float* __restrict__ lb, const float* __restrict__ kw,
                 const float* __restrict__ vw) {
    __shared__ float kws[2048], vws[2048], gs[32], bs[32];
    const int tid = threadIdx.x;
    for (int i = tid; i < 2048; i += 256) { kws[i] = kw[i]; vws[i] = vw[i]; }
    if (tid < 32) { gs[tid] = lg[tid]; bs[tid] = lb[tid]; }
    __syncthreads();
    const int b = blockIdx.y;
    const int j = blockIdx.x * 256 + tid;
    if (j >= N3) return;
    float xv[32];
    float s = 0.f;
#pragma unroll
    for (int c = 0; c < 32; c++) { xv[c] = x[(b * 32 + c) * N3 + j]; s += xv[c]; }
    const float m = s * (1.f / 32.f);
    float vs = 0.f;
#pragma unroll
    for (int c = 0; c < 32; c++) { float d = xv[c] - m; vs += d * d; }
    const float inv = rsqrtf(vs * (1.f / 32.f) + 1e-5f);
    ull xp[16];
#pragma unroll
    for (int c2 = 0; c2 < 16; c2++) {
        float a0 = (xv[2 * c2] - m) * inv * gs[2 * c2] + bs[2 * c2];
        float a1 = (xv[2 * c2 + 1] - m) * inv * gs[2 * c2 + 1] + bs[2 * c2 + 1];
        xp[c2] = pk(a0, a1);
    }
#pragma unroll 4
    for (int d = 0; d < 64; d++) {
        const ull* k8 = (const ull*)(kws + d * 32);
        const ull* v8 = (const ull*)(vws + d * 32);
        ull ka = 0ull, va = 0ull;
#pragma unroll
        for (int c2 = 0; c2 < 16; c2++) {
            fma2(ka, xp[c2], k8[c2], ka);
            fma2(va, xp[c2], v8[c2], va);
        }
        float2 kp = unpk(ka), vp = unpk(va);
        g_k[(b * 64 + d) * N3 + j] = kp.x + kp.y;
        g_v[(b * 64 + d) * N3 + j] = vp.x + vp.y;
    }
}

// =====================================================================
// q projection
// =====================================================================
__global__ __launch_bounds__(256)
void q_kernel(const float* __restrict__ slots, const float* __restrict__ lg,
              const float* __restrict__ lb, const float* __restrict__ qw) {
    __shared__ float s[1024], qws[4096], gs[64], bs[64], mm[16], iv[16];
    const int tid = threadIdx.x;
    for (int i = tid; i < 1024; i += 256) { s[i] = slots[i]; g_upd[i] = 0.f; }
    for (int i = tid; i < 4096; i += 256) qws[i] = qw[i];
    if (tid < 64) { gs[tid] = lg[tid]; bs[tid] = lb[tid]; }
    if (tid < 16) g_rowsum[tid] = 0.f;
    __syncthreads();
    if (tid < 16) {
        float sum = 0.f;
        for (int d = 0; d < 64; d++) sum += s[tid * 64 + d];
        float m = sum * (1.f / 64.f);
        float vs = 0.f;
        for (int d = 0; d < 64; d++) { float t = s[tid * 64 + d] - m; vs += t * t; }
        mm[tid] = m;
        iv[tid] = rsqrtf(vs * (1.f / 64.f) + 1e-5f);
    }
    __syncthreads();
    for (int k = 0; k < 4; k++) {
        int o = k * 256 + tid;
        int r = o >> 6, d = o & 63;
        float m = mm[r], inv = iv[r];
        float acc = 0.f;
#pragma unroll
        for (int c = 0; c < 64; c++)
            acc += ((s[r * 64 + c] - m) * inv * gs[c] + bs[c]) * qws[d * 64 + c];
        g_q[o] = acc * 0.125f;
    }
}

// =====================================================================
// fused attention iteration
// =====================================================================
__global__ __launch_bounds__(256)
void attn_kernel(float* __restrict__ attn_out) {
    extern __shared__ float sm[];
    float* qs = sm;
    float* as = sm + 512;
    float* vs = sm + 2560;
    const int tid  = threadIdx.x;
    const int b    = blockIdx.y;
    const int dd   = tid & 63;
    const int ib   = tid >> 6;
    const int wid  = tid >> 5;
    const int lane = tid & 31;
    for (int i = tid; i < 512; i += 256) qs[i] = g_q[b * 512 + i];

    float acc0 = 0.f, acc1 = 0.f, rs = 0.f;
    const int nch = (N3 + 255) >> 8;
    for (int c = blockIdx.x; c < nch; c += gridDim.x) {
        const int j0 = c << 8;
        const int j  = j0 + tid;
        __syncthreads();
        float a[8];
        if (j < N3) {
            float dots[8];
#pragma unroll
            for (int i = 0; i < 8; i++) dots[i] = 0.f;
#pragma unroll 16
            for (int d = 0; d < 64; d++) {
                float kv = g_k[(b * 64 + d) * N3 + j];
#pragma unroll
                for (int i = 0; i < 8; i++) dots[i] += qs[i * 64 + d] * kv;
            }
            float mx = dots[0];
#pragma unroll
            for (int i = 1; i < 8; i++) mx = fmaxf(mx, dots[i]);
            float ssum = 0.f;
#pragma unroll
            for (int i = 0; i < 8; i++) { a[i] = expf(dots[i] - mx); ssum += a[i]; }
            const float rinv = 1.f / ssum;
#pragma unroll
            for (int i = 0; i < 8; i++) a[i] = a[i] * rinv + 1e-8f;
            if (attn_out) {
#pragma unroll
                for (int i = 0; i < 8; i++)
                    attn_out[(b * 8 + i) * N3 + j] = a[i];
            }
        } else {
#pragma unroll
            for (int i = 0; i < 8; i++) a[i] = 0.f;
        }
#pragma unroll
        for (int i = 0; i < 8; i++) as[i * 256 + tid] = a[i];
        for (int idx = tid; idx < 64 * 256; idx += 256) {
            int d  = idx >> 8, jj = idx & 255;
            int jg = j0 + jj;
            vs[d * 257 + jj] = (jg < N3) ? g_v[(b * 64 + d) * N3 + jg] : 0.f;
        }
        __syncthreads();
        {
            float p = 0.f;
#pragma unroll
            for (int k = 0; k < 8; k++) p += as[wid * 256 + lane + k * 32];
#pragma unroll
            for (int off = 16; off; off >>= 1) p += __shfl_xor_sync(0xffffffffu, p, off);
            rs += p;
        }
        const float* ap0 = as + ib * 256;
        const float* ap1 = as + (ib + 4) * 256;
        const float* vp  = vs + dd * 257;
#pragma unroll 8
        for (int jj = 0; jj < 256; jj++) {
            float vv = vp[jj];
            acc0 += ap0[jj] * vv;
            acc1 += ap1[jj] * vv;
        }
    }
    atomicAdd(&g_upd[(b * 8 + ib) * 64 + dd], acc0);
    atomicAdd(&g_upd[(b * 8 + ib + 4) * 64 + dd], acc1);
    if (lane == 0) atomicAdd(&g_rowsum[b * 8 + wid], rs);
}

// =====================================================================
// GRU cell + LN + MLP residual
// =====================================================================
__global__ __launch_bounds__(512)
void gru_kernel(const float* __restrict__ slots_prev,
                const float* __restrict__ wih, const float* __restrict__ whh,
                const float* __restrict__ bih, const float* __restrict__ bhh,
                const float* __restrict__ lng, const float* __restrict__ lnb,
                const float* __restrict__ w1, const float* __restrict__ rb1,
                const float* __restrict__ w2, const float* __restrict__ rb2,
                float* __restrict__ slots_final) {
    __shared__ float S[9216];
    float* u  = S;
    float* h  = S + 1024;
    float* xg = S + 2048;
    float* hg = S + 5120;
    float* nh = S + 8192;
    float* normed = S + 2048;
    float* t1     = S + 5120;
    const int tid = threadIdx.x;

    for (int k = 0; k < 2; k++) {
        int idx = k * 512 + tid;
        int r = idx >> 6;
        u[idx] = g_upd[idx] / g_rowsum[r];
        h[idx] = slots_prev[idx];
    }
    __syncthreads();
    for (int k = 0; k < 6; k++) {
        int p = k * 512 + tid;
        int r = p / 192, c = p - r * 192;
        float xa = bih[c], ha = bhh[c];
        const float* wr = wih + c * 64;
        const float* hr = whh + c * 64;
#pragma unroll 16
        for (int d = 0; d < 64; d++) {
            xa += u[r * 64 + d] * wr[d];
            ha += h[r * 64 + d] * hr[d];
        }
        xg[p] = xa; hg[p] = ha;
    }
    __syncthreads();
    for (int k = 0; k < 2; k++) {
        int idx = k * 512 + tid;
        int r = idx >> 6, d = idx & 63;
        float rg = 1.f / (1.f + expf(-(xg[r * 192 + d] + hg[r * 192 + d])));
        float z  = 1.f / (1.f + expf(-(xg[r * 192 + 64 + d] + hg[r * 192 + 64 + d])));
        float n  = tanhf(xg[r * 192 + 128 + d] + rg * hg[r * 192 + 128 + d]);
        nh[idx] = (1.f - z) * n + z * h[idx];
    }
    __syncthreads();
    {
        const int w = tid >> 5, lane = tid & 31;
        float e0 = nh[w * 64 + lane], e1 = nh[w * 64 + 32 + lane];
        float s = e0 + e1;
#pragma unroll
        for (int off = 16; off; off >>= 1) s += __shfl_xor_sync(0xffffffffu, s, off);
        float m = s * (1.f / 64.f);
        float d0 = e0 - m, d1 = e1 - m;
        float vq = d0 * d0 + d1 * d1;
#pragma unroll
        for (int off = 16; off; off >>= 1) vq += __shfl_xor_sync(0xffffffffu, vq, off);
        float inv = rsqrtf(vq * (1.f / 64.f) + 1e-5f);
        normed[w * 64 + lane]      = d0 * inv * lng[lane] + lnb[lane];
        normed[w * 64 + 32 + lane] = d1 * inv * lng[32 + lane] + lnb[32 + lane];
    }
    __syncthreads();
    for (int k = 0; k < 4; k++) {
        int p = k * 512 + tid;
        int r = p >> 7, c = p & 127;
        float acc = rb1[c];
        const float* wr = w1 + c * 64;
#pragma unroll 16
        for (int d = 0; d < 64; d++) acc += normed[r * 64 + d] * wr[d];
        t1[p] = fmaxf(acc, 0.f);
    }
    __syncthreads();
    for (int k = 0; k < 2; k++) {
        int idx = k * 512 + tid;
        int r = idx >> 6, d = idx & 63;
        float acc = rb2[d];
        const float* wr = w2 + d * 128;
#pragma unroll 16
        for (int c = 0; c < 128; c++) acc += t1[r * 128 + c] * wr[c];
        float val = nh[idx] + acc;
        g_slots[idx] = val;
        if (slots_final) slots_final[idx] = val;
    }
}

// =====================================================================
// host driver
// =====================================================================
extern "C" void kernel_launch(void* const* d_in, const int* in_sizes, int n_in,
                              void* d_out, int out_size) {
    (void)in_sizes; (void)n_in; (void)out_size;
    const float* p_slots = (const float*)d_in[0];
    const float* p_oin   = (const float*)d_in[1];
    const float* w1  = (const float*)d_in[2];
    const float* b1  = (const float*)d_in[3];
    const float* w2  = (const float*)d_in[4];
    const float* b2  = (const float*)d_in[5];
    const float* w3  = (const float*)d_in[6];
    const float* b3  = (const float*)d_in[7];
    const float* kw  = (const float*)d_in[8];
    const float* vw  = (const float*)d_in[9];
    const float* qlg = (const float*)d_in[10];
    const float* qlb = (const float*)d_in[11];
    const float* qw  = (const float*)d_in[12];
    const float* gwih = (const float*)d_in[13];
    const float* gwhh = (const float*)d_in[14];
    const float* gbih = (const float*)d_in[15];
    const float* gbhh = (const float*)d_in[16];
    const float* rlg = (const float*)d_in[17];
    const float* rlb = (const float*)d_in[18];
    const float* rw1 = (const float*)d_in[19];
    const float* rb1 = (const float*)d_in[20];
    const float* rw2 = (const float*)d_in[21];
    const float* rb2 = (const float*)d_in[22];
    const float* flg = (const float*)d_in[23];
    const float* flb = (const float*)d_in[24];
    float* out = (float*)d_out;

    const size_t smem4  = (size_t)(4 * 27 * 32 + 8192) * sizeof(float);
    const size_t smemA  = (size_t)(512 + 2048 + 64 * 257) * sizeof(float);
    cudaFuncSetAttribute(conv3d_kernel<4>, cudaFuncAttributeMaxDynamicSharedMemorySize, (int)smem4);
    cudaFuncSetAttribute(conv_mma_kernel, cudaFuncAttributeMaxDynamicSharedMemorySize, SMEM_MMA);
    cudaFuncSetAttribute(attn_kernel, cudaFuncAttributeMaxDynamicSharedMemorySize, (int)smemA);

    float *buf1, *buf2, *slots_g;
    __nv_bfloat16 *B2p, *B3p;
    cudaGetSymbolAddress((void**)&buf1, g_buf1);
    cudaGetSymbolAddress((void**)&buf2, g_buf2);
    cudaGetSymbolAddress((void**)&slots_g, g_slots);
    cudaGetSymbolAddress((void**)&B2p, g_B2p);
    cudaGetSymbolAddress((void**)&B3p, g_B3p);

    // weight prep for tensor-core convs
    prepB_kernel<<<108, 256>>>(w2, B2p);
    prepB_kernel<<<108, 256>>>(w3, B3p);

    // conv1: 80 -> 78 (scalar, CIN=4)
    conv3d_kernel<4><<<dim3(10 * 10, 20, 2), 256, smem4>>>(p_oin, w1, b1, buf1, 80);
    // conv2: 78 -> 76 (mma.sync)
    conv_mma_kernel<<<148, 256, SMEM_MMA>>>(buf1, B2p, b2, buf2, 78);
    // conv3: 76 -> 74 (mma.sync)
    conv_mma_kernel<<<148, 256, SMEM_MMA>>>(buf2, B3p, b3, buf1, 76);
    // feature LN + k/v projection
    lnkv_kernel<<<dim3((N3 + 255) / 256, 2), 256>>>(buf1, flg, flb, kw, vw);

    for (int it = 0; it < 3; it++) {
        const float* sp = (it == 0) ? p_slots : slots_g;
        q_kernel<<<1, 256>>>(sp, qlg, qlb, qw);
        attn_kernel<<<dim3(222, 2), 256, smemA>>>((it == 2) ? (out + 1024) : (float*)0);
        gru_kernel<<<1, 512>>>(sp, gwih, gwhh, gbih, gbhh, rlg, rlb,
                               rw1, rb1, rw2, rb2, (it == 2) ? out : (float*)0);
    }
}

// round 6
// speedup vs baseline: 1.3976x; 1.2717x over previous
#include <cuda_runtime.h>
#include <cuda_bf16.h>
#include <math.h>
#include <stdint.h>

// ---------------- problem constants ----------------
#define N3   405224   // 74^3

typedef unsigned long long ull;

// ---------------- f32x2 packed helpers (lnkv) ----------------
__device__ __forceinline__ ull pk(float lo, float hi) {
    ull r; asm("mov.b64 %0, {%1,%2};" : "=l"(r) : "f"(lo), "f"(hi)); return r;
}
__device__ __forceinline__ float2 unpk(ull p) {
    float2 f; asm("mov.b64 {%0,%1}, %2;" : "=f"(f.x), "=f"(f.y) : "l"(p)); return f;
}
__device__ __forceinline__ void fma2(ull& d, ull a, ull b, ull c) {
    asm("fma.rn.f32x2 %0, %1, %2, %3;" : "=l"(d) : "l"(a), "l"(b), "l"(c));
}

// ---------------- device scratch ----------------
__device__ float g_buf1[2 * 32 * 78 * 78 * 78];   // conv1 out / conv3 out
__device__ float g_buf2[2 * 32 * 76 * 76 * 76];   // conv2 out
__device__ float g_k[2 * 64 * N3];
__device__ float g_v[2 * 64 * N3];
__device__ float g_slots[1024];
__device__ float g_q[1024];
__device__ float g_upd[1024];
__device__ float g_rowsum[16];
__device__ __nv_bfloat16 g_B2p[27 * 32 * 64];     // [tap][cout][hi32|lo32]
__device__ __nv_bfloat16 g_B3p[27 * 32 * 64];

// =====================================================================
// Weight prep: w[cout][cin][27] fp32 -> [tap][cout][hi(32)|lo(32)] bf16
// =====================================================================
__global__ void prepB_kernel(const float* __restrict__ w, __nv_bfloat16* __restrict__ Bg) {
    int idx = blockIdx.x * 256 + threadIdx.x;   // 0..27647
    if (idx >= 27648) return;
    int t = idx >> 10;
    int r = idx & 1023;
    int n = r >> 5;
    int ci = r & 31;
    float x = w[(n * 32 + ci) * 27 + t];
    __nv_bfloat16 hi = __float2bfloat16(x);
    float rem = x - __bfloat162float(hi);
    __nv_bfloat16 lo = __float2bfloat16(rem);
    Bg[(t * 32 + n) * 64 + ci] = hi;
    Bg[(t * 32 + n) * 64 + 32 + ci] = lo;
}

// =====================================================================
// mma.sync bf16 split-2 implicit-GEMM conv3d 3x3x3 VALID, 32ci->32co, relu.
// Persistent grid; CTA tile = 256 tokens (4d x 8h x 8w) x 32 cout.
// Product-major MMA issue: consecutive HMMAs hit distinct accumulators.
// =====================================================================
#define BROW_W 36                          // words per padded B row
#define BROW_B (BROW_W * 4)
#define B_BYTES (27 * 32 * BROW_B)         // 124416
#define PROW_W 36
#define PROW_B (PROW_W * 4)
#define P_OFF  B_BYTES
#define P_BYTES (600 * PROW_B)             // 86400
#define SMEM_MMA (P_OFF + P_BYTES)         // 210816

#define MMA_BF16(d, a, b)                                                  \
    asm volatile("mma.sync.aligned.m16n8k16.row.col.f32.bf16.bf16.f32 "    \
                 "{%0,%1,%2,%3}, {%4,%5,%6,%7}, {%8,%9}, {%0,%1,%2,%3};"   \
                 : "+f"(d[0]), "+f"(d[1]), "+f"(d[2]), "+f"(d[3])          \
                 : "r"(a[0]), "r"(a[1]), "r"(a[2]), "r"(a[3]),             \
                   "r"(b[0]), "r"(b[1]))

__global__ __launch_bounds__(256)
void conv_mma_kernel(const float* __restrict__ in, const __nv_bfloat16* __restrict__ Bg,
                     const float* __restrict__ bias, float* __restrict__ out, int Di) {
    const int Do = Di - 2;
    extern __shared__ char smem[];
    __shared__ float s_bias[32];
    const int tid  = threadIdx.x;
    const int wid  = tid >> 5;
    const int lane = tid & 31;
    const int grp  = lane >> 2;       // 0..7
    const int tig  = lane & 3;        // 0..3

    // copy B into smem with row padding (32 -> 36 words)
    {
        const uint32_t* src = (const uint32_t*)Bg;
        uint32_t* dst = (uint32_t*)smem;
        for (int i = tid; i < 27648; i += 256) {
            int row = i >> 5, w = i & 31;
            dst[row * BROW_W + w] = src[i];
        }
    }
    if (tid < 32) s_bias[tid] = bias[tid];
    __syncthreads();

    // per-thread token -> patch-row bases (2 mtiles x 2 row-halves)
    const int wbase = wid * 32;
    int srow[2][2];
    int tok[2][2];
#pragma unroll
    for (int mt = 0; mt < 2; mt++)
#pragma unroll
        for (int hf = 0; hf < 2; hf++) {
            int t = wbase + mt * 16 + grp + hf * 8;
            tok[mt][hf] = t;
            int d = t >> 6, h = (t >> 3) & 7, w = t & 7;
            srow[mt][hf] = d * 100 + h * 10 + w;
        }

    // precompute fill-loop spatial decomposition (each thread owns <=3 s-slots)
    int pd_[3], ph_[3], pw_[3], pofs_[3];
    bool sv_[3];
#pragma unroll
    for (int q = 0; q < 3; q++) {
        int s = tid + 256 * q;
        sv_[q] = (s < 600);
        int ss = sv_[q] ? s : 0;
        pd_[q] = ss / 100; int r2 = ss - pd_[q] * 100;
        ph_[q] = r2 / 10;  pw_[q] = r2 - ph_[q] * 10;
        pofs_[q] = ss * PROW_B;
    }

    const int nd = (Do + 3) >> 2, nhw = (Do + 7) >> 3;
    const int ntb = nd * nhw * nhw;
    const int DiDi = Di * Di;
    char* patch = smem + P_OFF;

    for (int ti = blockIdx.x; ti < 2 * ntb; ti += gridDim.x) {
        const int b = ti / ntb;
        int r = ti - b * ntb;
        const int td = r / (nhw * nhw); r -= td * (nhw * nhw);
        const int th = r / nhw, tw = r - (r / nhw) * nhw;
        const int d0 = td * 4, h0 = th * 8, w0 = tw * 8;

        __syncthreads();   // previous tile's reads done
        // ---- patch fill: 600 spatial rows x 32 ci, hi|lo bf16 ----
#pragma unroll
        for (int q = 0; q < 3; q++) {
            if (!sv_[q]) continue;
            const int gd = d0 + pd_[q], gh = h0 + ph_[q], gw = w0 + pw_[q];
            const bool ok = (gd < Di) & (gh < Di) & (gw < Di);
            const float* src = in + (size_t)b * 32 * Di * DiDi + (size_t)(gd * Di + gh) * Di + gw;
            char* pdst = patch + pofs_[q];
#pragma unroll 4
            for (int ci = 0; ci < 32; ci++) {
                float x = ok ? src[(size_t)ci * Di * DiDi] : 0.f;
                __nv_bfloat16 hi = __float2bfloat16(x);
                float rem = x - __bfloat162float(hi);
                __nv_bfloat16 lo = __float2bfloat16(rem);
                *(__nv_bfloat16*)(pdst + ci * 2) = hi;
                *(__nv_bfloat16*)(pdst + 64 + ci * 2) = lo;
            }
        }
        __syncthreads();

        float acc[2][4][4];
#pragma unroll
        for (int mt = 0; mt < 2; mt++)
#pragma unroll
            for (int nt = 0; nt < 4; nt++)
#pragma unroll
                for (int q = 0; q < 4; q++) acc[mt][nt][q] = 0.f;

#pragma unroll 1
        for (int t = 0; t < 27; t++) {
            const int kd = t / 9; const int r9 = t - kd * 9;
            const int kh = r9 / 3; const int kw = r9 - kh * 3;
            const int toff = kd * 100 + kh * 10 + kw;
            const char* brow = smem + (size_t)t * 32 * BROW_B;

            // ---- load ALL fragments for both K-halves of this tap ----
            uint32_t af[2][2][2][4];   // [ks][mt][sp][4]
            uint32_t bf[2][4][2][2];   // [ks][nt][sp][2]
#pragma unroll
            for (int ks = 0; ks < 2; ks++) {
#pragma unroll
                for (int mt = 0; mt < 2; mt++) {
                    const char* p0 = patch + (size_t)(srow[mt][0] + toff) * PROW_B + ks * 32 + tig * 4;
                    const char* p1 = patch + (size_t)(srow[mt][1] + toff) * PROW_B + ks * 32 + tig * 4;
#pragma unroll
                    for (int sp = 0; sp < 2; sp++) {
                        af[ks][mt][sp][0] = *(const uint32_t*)(p0 + sp * 64);
                        af[ks][mt][sp][1] = *(const uint32_t*)(p1 + sp * 64);
                        af[ks][mt][sp][2] = *(const uint32_t*)(p0 + sp * 64 + 16);
                        af[ks][mt][sp][3] = *(const uint32_t*)(p1 + sp * 64 + 16);
                    }
                }
#pragma unroll
                for (int nt = 0; nt < 4; nt++) {
                    const char* pb = brow + (size_t)(nt * 8 + grp) * BROW_B + ks * 32 + tig * 4;
#pragma unroll
                    for (int sp = 0; sp < 2; sp++) {
                        bf[ks][nt][sp][0] = *(const uint32_t*)(pb + sp * 64);
                        bf[ks][nt][sp][1] = *(const uint32_t*)(pb + sp * 64 + 16);
                    }
                }
            }

            // ---- product-major issue: same accumulator revisited only
            //      after 8 intervening independent HMMAs ----
#pragma unroll
            for (int ks = 0; ks < 2; ks++)
#pragma unroll
                for (int mt = 0; mt < 2; mt++)
#pragma unroll
                    for (int nt = 0; nt < 4; nt++)
                        MMA_BF16(acc[mt][nt], af[ks][mt][0], bf[ks][nt][0]);   // hi*hi
#pragma unroll
            for (int ks = 0; ks < 2; ks++)
#pragma unroll
                for (int mt = 0; mt < 2; mt++)
#pragma unroll
                    for (int nt = 0; nt < 4; nt++)
                        MMA_BF16(acc[mt][nt], af[ks][mt][1], bf[ks][nt][0]);   // lo*hi
#pragma unroll
            for (int ks = 0; ks < 2; ks++)
#pragma unroll
                for (int mt = 0; mt < 2; mt++)
#pragma unroll
                    for (int nt = 0; nt < 4; nt++)
                        MMA_BF16(acc[mt][nt], af[ks][mt][0], bf[ks][nt][1]);   // hi*lo
        }

        // ---- epilogue: bias + relu + predicated store ----
#pragma unroll
        for (int mt = 0; mt < 2; mt++)
#pragma unroll
            for (int nt = 0; nt < 4; nt++)
#pragma unroll
                for (int q = 0; q < 4; q++) {
                    int t = tok[mt][q >> 1];
                    int c = nt * 8 + tig * 2 + (q & 1);
                    int dd = t >> 6, hh = (t >> 3) & 7, ww = t & 7;
                    int od = d0 + dd, oh = h0 + hh, ow = w0 + ww;
                    if (od < Do && oh < Do && ow < Do) {
                        float v = acc[mt][nt][q] + s_bias[c];
                        out[(((size_t)(b * 32 + c) * Do + od) * Do + oh) * Do + ow] =
                            v > 0.f ? v : 0.f;
                    }
                }
    }
}

// =====================================================================
// Scalar conv for conv1 (CIN=4).
// =====================================================================
template <int CIN>
__global__ __launch_bounds__(256)
void conv3d_kernel(const float* __restrict__ in, const float* __restrict__ wg,
                   const float* __restrict__ bias, float* __restrict__ out,
                   int Di) {
    const int Do = Di - 2;
    const int tid = threadIdx.x;
    const int b  = blockIdx.z;
    const int nW = (Do + 7) >> 3;
    const int h0 = (blockIdx.x / nW) * 8;
    const int w0 = (blockIdx.x % nW) * 8;
    const int d0 = blockIdx.y * 4;

    extern __shared__ float smemf[];
    float* ws    = smemf;
    float* patch = smemf + CIN * 27 * 32;

    const int WTOT = 32 * CIN * 27;
    for (int idx = tid; idx < WTOT; idx += 256) {
        int co = idx / (CIN * 27);
        int r  = idx - co * (CIN * 27);
        ws[r * 32 + co] = wg[idx];
    }
    for (int idx = tid; idx < CIN * 600; idx += 256) {
        int ci = idx / 600;
        int r  = idx - ci * 600;
        int dd = r / 100;  int r2 = r - dd * 100;
        int hh = r2 / 10;  int ww = r2 - hh * 10;
        int gd = d0 + dd, gh = h0 + hh, gw = w0 + ww;
        float val = 0.f;
        if (gd < Di && gh < Di && gw < Di)
            val = in[(((b * CIN + ci) * Di + gd) * Di + gh) * Di + gw];
        patch[idx] = val;
    }
    __syncthreads();

    const int cout = tid >> 3;
    const int hg   = tid & 7;
    const float bv = bias[cout];

    float acc[4][8];
#pragma unroll
    for (int i = 0; i < 4; i++)
#pragma unroll
        for (int j = 0; j < 8; j++) acc[i][j] = 0.f;

    for (int ci = 0; ci < CIN; ci++) {
        float wr[27];
#pragma unroll
        for (int t = 0; t < 27; t++) wr[t] = ws[(ci * 27 + t) * 32 + cout];
        const float* pbase = patch + ci * 600;
#pragma unroll
        for (int kh = 0; kh < 3; kh++) {
            const float* rowb = pbase + (hg + kh) * 10;
#pragma unroll
            for (int dd = 0; dd < 6; dd++) {
                float row[10];
                const float2* rp = (const float2*)(rowb + dd * 100);
#pragma unroll
                for (int j = 0; j < 5; j++) ((float2*)row)[j] = rp[j];
#pragma unroll
                for (int kd = 0; kd < 3; kd++) {
                    const int dlo = dd - kd;
                    if (dlo >= 0 && dlo < 4) {
#pragma unroll
                        for (int kw = 0; kw < 3; kw++) {
                            float wv = wr[kd * 9 + kh * 3 + kw];
#pragma unroll
                            for (int w = 0; w < 8; w++)
                                acc[dlo][w] += wv * row[w + kw];
                        }
                    }
                }
            }
        }
    }
    __syncthreads();
#pragma unroll
    for (int dd = 0; dd < 4; dd++)
#pragma unroll
        for (int w = 0; w < 8; w++) {
            float v = acc[dd][w] + bv;
            patch[cout * 256 + dd * 64 + hg * 8 + w] = v > 0.f ? v : 0.f;
        }
    __syncthreads();
    const int DoDo = Do * Do;
    for (int idx = tid; idx < 8192; idx += 256) {
        int co = idx >> 8;
        int r  = idx & 255;
        int dd = r >> 6;
        int hh = (r >> 3) & 7;
        int w  = r & 7;
        int od = d0 + dd, oh = h0 + hh, ow = w0 + w;
        if (od < Do && oh < Do && ow < Do)
            out[((b * 32 + co) * Do + od) * DoDo + oh * Do + ow] = patch[idx];
    }
}

// =====================================================================
// feature LN + k/v projection
// =====================================================================
__global__ __launch_bounds__(256)
void lnkv_kernel(const float* __restrict__ x, const float* __restrict__ lg,
                 const float* __restrict__ lb, const float* __restrict__ kw,
                 const float* __restrict__ vw) {
    __shared__ float kws[2048], vws[2048], gs[32], bs[32];
    const int tid = threadIdx.x;
    for (int i = tid; i < 2048; i += 256) { kws[i] = kw[i]; vws[i] = vw[i]; }
    if (tid < 32) { gs[tid] = lg[tid]; bs[tid] = lb[tid]; }
    __syncthreads();
    const int b = blockIdx.y;
    const int j = blockIdx.x * 256 + tid;
    if (j >= N3) return;
    float xv[32];
    float s = 0.f;
#pragma unroll
    for (int c = 0; c < 32; c++) { xv[c] = x[(b * 32 + c) * N3 + j]; s += xv[c]; }
    const float m = s * (1.f / 32.f);
    float vs = 0.f;
#pragma unroll
    for (int c = 0; c < 32; c++) { float d = xv[c] - m; vs += d * d; }
    const float inv = rsqrtf(vs * (1.f / 32.f) + 1e-5f);
    ull xp[16];
#pragma unroll
    for (int c2 = 0; c2 < 16; c2++) {
        float a0 = (xv[2 * c2] - m) * inv * gs[2 * c2] + bs[2 * c2];
        float a1 = (xv[2 * c2 + 1] - m) * inv * gs[2 * c2 + 1] + bs[2 * c2 + 1];
        xp[c2] = pk(a0, a1);
    }
#pragma unroll 4
    for (int d = 0; d < 64; d++) {
        const ull* k8 = (const ull*)(kws + d * 32);
        const ull* v8 = (const ull*)(vws + d * 32);
        ull ka = 0ull, va = 0ull;
#pragma unroll
        for (int c2 = 0; c2 < 16; c2++) {
            fma2(ka, xp[c2], k8[c2], ka);
            fma2(va, xp[c2], v8[c2], va);
        }
        float2 kp = unpk(ka), vp = unpk(va);
        g_k[(b * 64 + d) * N3 + j] = kp.x + kp.y;
        g_v[(b * 64 + d) * N3 + j] = vp.x + vp.y;
    }
}

// =====================================================================
// q projection
// =====================================================================
__global__ __launch_bounds__(256)
void q_kernel(const float* __restrict__ slots, const float* __restrict__ lg,
              const float* __restrict__ lb, const float* __restrict__ qw) {
    __shared__ float s[1024], qws[4096], gs[64], bs[64], mm[16], iv[16];
    const int tid = threadIdx.x;
    for (int i = tid; i < 1024; i += 256) { s[i] = slots[i]; g_upd[i] = 0.f; }
    for (int i = tid; i < 4096; i += 256) qws[i] = qw[i];
    if (tid < 64) { gs[tid] = lg[tid]; bs[tid] = lb[tid]; }
    if (tid < 16) g_rowsum[tid] = 0.f;
    __syncthreads();
    if (tid < 16) {
        float sum = 0.f;
        for (int d = 0; d < 64; d++) sum += s[tid * 64 + d];
        float m = sum * (1.f / 64.f);
        float vs = 0.f;
        for (int d = 0; d < 64; d++) { float t = s[tid * 64 + d] - m; vs += t * t; }
        mm[tid] = m;
        iv[tid] = rsqrtf(vs * (1.f / 64.f) + 1e-5f);
    }
    __syncthreads();
    for (int k = 0; k < 4; k++) {
        int o = k * 256 + tid;
        int r = o >> 6, d = o & 63;
        float m = mm[r], inv = iv[r];
        float acc = 0.f;
#pragma unroll
        for (int c = 0; c < 64; c++)
            acc += ((s[r * 64 + c] - m) * inv * gs[c] + bs[c]) * qws[d * 64 + c];
        g_q[o] = acc * 0.125f;
    }
}

// =====================================================================
// fused attention iteration
// =====================================================================
__global__ __launch_bounds__(256)
void attn_kernel(float* __restrict__ attn_out) {
    extern __shared__ float sm[];
    float* qs = sm;
    float* as = sm + 512;
    float* vs = sm + 2560;
    const int tid  = threadIdx.x;
    const int b    = blockIdx.y;
    const int dd   = tid & 63;
    const int ib   = tid >> 6;
    const int wid  = tid >> 5;
    const int lane = tid & 31;
    for (int i = tid; i < 512; i += 256) qs[i] = g_q[b * 512 + i];

    float acc0 = 0.f, acc1 = 0.f, rs = 0.f;
    const int nch = (N3 + 255) >> 8;
    for (int c = blockIdx.x; c < nch; c += gridDim.x) {
        const int j0 = c << 8;
        const int j  = j0 + tid;
        __syncthreads();
        float a[8];
        if (j < N3) {
            float dots[8];
#pragma unroll
            for (int i = 0; i < 8; i++) dots[i] = 0.f;
#pragma unroll 16
            for (int d = 0; d < 64; d++) {
                float kv = g_k[(b * 64 + d) * N3 + j];
#pragma unroll
                for (int i = 0; i < 8; i++) dots[i] += qs[i * 64 + d] * kv;
            }
            float mx = dots[0];
#pragma unroll
            for (int i = 1; i < 8; i++) mx = fmaxf(mx, dots[i]);
            float ssum = 0.f;
#pragma unroll
            for (int i = 0; i < 8; i++) { a[i] = expf(dots[i] - mx); ssum += a[i]; }
            const float rinv = 1.f / ssum;
#pragma unroll
            for (int i = 0; i < 8; i++) a[i] = a[i] * rinv + 1e-8f;
            if (attn_out) {
#pragma unroll
                for (int i = 0; i < 8; i++)
                    attn_out[(b * 8 + i) * N3 + j] = a[i];
            }
        } else {
#pragma unroll
            for (int i = 0; i < 8; i++) a[i] = 0.f;
        }
#pragma unroll
        for (int i = 0; i < 8; i++) as[i * 256 + tid] = a[i];
        for (int idx = tid; idx < 64 * 256; idx += 256) {
            int d  = idx >> 8, jj = idx & 255;
            int jg = j0 + jj;
            vs[d * 257 + jj] = (jg < N3) ? g_v[(b * 64 + d) * N3 + jg] : 0.f;
        }
        __syncthreads();
        {
            float p = 0.f;
#pragma unroll
            for (int k = 0; k < 8; k++) p += as[wid * 256 + lane + k * 32];
#pragma unroll
            for (int off = 16; off; off >>= 1) p += __shfl_xor_sync(0xffffffffu, p, off);
            rs += p;
        }
        const float* ap0 = as + ib * 256;
        const float* ap1 = as + (ib + 4) * 256;
        const float* vp  = vs + dd * 257;
#pragma unroll 8
        for (int jj = 0; jj < 256; jj++) {
            float vv = vp[jj];
            acc0 += ap0[jj] * vv;
            acc1 += ap1[jj] * vv;
        }
    }
    atomicAdd(&g_upd[(b * 8 + ib) * 64 + dd], acc0);
    atomicAdd(&g_upd[(b * 8 + ib + 4) * 64 + dd], acc1);
    if (lane == 0) atomicAdd(&g_rowsum[b * 8 + wid], rs);
}

// =====================================================================
// GRU cell + LN + MLP residual
// =====================================================================
__global__ __launch_bounds__(512)
void gru_kernel(const float* __restrict__ slots_prev,
                const float* __restrict__ wih, const float* __restrict__ whh,
                const float* __restrict__ bih, const float* __restrict__ bhh,
                const float* __restrict__ lng, const float* __restrict__ lnb,
                const float* __restrict__ w1, const float* __restrict__ rb1,
                const float* __restrict__ w2, const float* __restrict__ rb2,
                float* __restrict__ slots_final) {
    __shared__ float S[9216];
    float* u  = S;
    float* h  = S + 1024;
    float* xg = S + 2048;
    float* hg = S + 5120;
    float* nh = S + 8192;
    float* normed = S + 2048;
    float* t1     = S + 5120;
    const int tid = threadIdx.x;

    for (int k = 0; k < 2; k++) {
        int idx = k * 512 + tid;
        int r = idx >> 6;
        u[idx] = g_upd[idx] / g_rowsum[r];
        h[idx] = slots_prev[idx];
    }
    __syncthreads();
    for (int k = 0; k < 6; k++) {
        int p = k * 512 + tid;
        int r = p / 192, c = p - r * 192;
        float xa = bih[c], ha = bhh[c];
        const float* wr = wih + c * 64;
        const float* hr = whh + c * 64;
#pragma unroll 16
        for (int d = 0; d < 64; d++) {
            xa += u[r * 64 + d] * wr[d];
            ha += h[r * 64 + d] * hr[d];
        }
        xg[p] = xa; hg[p] = ha;
    }
    __syncthreads();
    for (int k = 0; k < 2; k++) {
        int idx = k * 512 + tid;
        int r = idx >> 6, d = idx & 63;
        float rg = 1.f / (1.f + expf(-(xg[r * 192 + d] + hg[r * 192 + d])));
        float z  = 1.f / (1.f + expf(-(xg[r * 192 + 64 + d] + hg[r * 192 + 64 + d])));
        float n  = tanhf(xg[r * 192 + 128 + d] + rg * hg[r * 192 + 128 + d]);
        nh[idx] = (1.f - z) * n + z * h[idx];
    }
    __syncthreads();
    {
        const int w = tid >> 5, lane = tid & 31;
        float e0 = nh[w * 64 + lane], e1 = nh[w * 64 + 32 + lane];
        float s = e0 + e1;
#pragma unroll
        for (int off = 16; off; off >>= 1) s += __shfl_xor_sync(0xffffffffu, s, off);
        float m = s * (1.f / 64.f);
        float d0 = e0 - m, d1 = e1 - m;
        float vq = d0 * d0 + d1 * d1;
#pragma unroll
        for (int off = 16; off; off >>= 1) vq += __shfl_xor_sync(0xffffffffu, vq, off);
        float inv = rsqrtf(vq * (1.f / 64.f) + 1e-5f);
        normed[w * 64 + lane]      = d0 * inv * lng[lane] + lnb[lane];
        normed[w * 64 + 32 + lane] = d1 * inv * lng[32 + lane] + lnb[32 + lane];
    }
    __syncthreads();
    for (int k = 0; k < 4; k++) {
        int p = k * 512 + tid;
        int r = p >> 7, c = p & 127;
        float acc = rb1[c];
        const float* wr = w1 + c * 64;
#pragma unroll 16
        for (int d = 0; d < 64; d++) acc += normed[r * 64 + d] * wr[d];
        t1[p] = fmaxf(acc, 0.f);
    }
    __syncthreads();
    for (int k = 0; k < 2; k++) {
        int idx = k * 512 + tid;
        int r = idx >> 6, d = idx & 63;
        float acc = rb2[d];
        const float* wr = w2 + d * 128;
#pragma unroll 16
        for (int c = 0; c < 128; c++) acc += t1[r * 128 + c] * wr[c];
        float val = nh[idx] + acc;
        g_slots[idx] = val;
        if (slots_final) slots_final[idx] = val;
    }
}

// =====================================================================
// host driver
// =====================================================================
extern "C" void kernel_launch(void* const* d_in, const int* in_sizes, int n_in,
                              void* d_out, int out_size) {
    (void)in_sizes; (void)n_in; (void)out_size;
    const float* p_slots = (const float*)d_in[0];
    const float* p_oin   = (const float*)d_in[1];
    const float* w1  = (const float*)d_in[2];
    const float* b1  = (const float*)d_in[3];
    const float* w2  = (const float*)d_in[4];
    const float* b2  = (const float*)d_in[5];
    const float* w3  = (const float*)d_in[6];
    const float* b3  = (const float*)d_in[7];
    const float* kw  = (const float*)d_in[8];
    const float* vw  = (const float*)d_in[9];
    const float* qlg = (const float*)d_in[10];
    const float* qlb = (const float*)d_in[11];
    const float* qw  = (const float*)d_in[12];
    const float* gwih = (const float*)d_in[13];
    const float* gwhh = (const float*)d_in[14];
    const float* gbih = (const float*)d_in[15];
    const float* gbhh = (const float*)d_in[16];
    const float* rlg = (const float*)d_in[17];
    const float* rlb = (const float*)d_in[18];
    const float* rw1 = (const float*)d_in[19];
    const float* rb1 = (const float*)d_in[20];
    const float* rw2 = (const float*)d_in[21];
    const float* rb2 = (const float*)d_in[22];
    const float* flg = (const float*)d_in[23];
    const float* flb = (const float*)d_in[24];
    float* out = (float*)d_out;

    const size_t smem4  = (size_t)(4 * 27 * 32 + 8192) * sizeof(float);
    const size_t smemA  = (size_t)(512 + 2048 + 64 * 257) * sizeof(float);
    cudaFuncSetAttribute(conv3d_kernel<4>, cudaFuncAttributeMaxDynamicSharedMemorySize, (int)smem4);
    cudaFuncSetAttribute(conv_mma_kernel, cudaFuncAttributeMaxDynamicSharedMemorySize, SMEM_MMA);
    cudaFuncSetAttribute(attn_kernel, cudaFuncAttributeMaxDynamicSharedMemorySize, (int)smemA);

    float *buf1, *buf2, *slots_g;
    __nv_bfloat16 *B2p, *B3p;
    cudaGetSymbolAddress((void**)&buf1, g_buf1);
    cudaGetSymbolAddress((void**)&buf2, g_buf2);
    cudaGetSymbolAddress((void**)&slots_g, g_slots);
    cudaGetSymbolAddress((void**)&B2p, g_B2p);
    cudaGetSymbolAddress((void**)&B3p, g_B3p);

    // weight prep for tensor-core convs
    prepB_kernel<<<108, 256>>>(w2, B2p);
    prepB_kernel<<<108, 256>>>(w3, B3p);

    // conv1: 80 -> 78 (scalar, CIN=4)
    conv3d_kernel<4><<<dim3(10 * 10, 20, 2), 256, smem4>>>(p_oin, w1, b1, buf1, 80);
    // conv2: 78 -> 76 (mma.sync)
    conv_mma_kernel<<<148, 256, SMEM_MMA>>>(buf1, B2p, b2, buf2, 78);
    // conv3: 76 -> 74 (mma.sync)
    conv_mma_kernel<<<148, 256, SMEM_MMA>>>(buf2, B3p, b3, buf1, 76);
    // feature LN + k/v projection
    lnkv_kernel<<<dim3((N3 + 255) / 256, 2), 256>>>(buf1, flg, flb, kw, vw);

    for (int it = 0; it < 3; it++) {
        const float* sp = (it == 0) ? p_slots : slots_g;
        q_kernel<<<1, 256>>>(sp, qlg, qlb, qw);
        attn_kernel<<<dim3(222, 2), 256, smemA>>>((it == 2) ? (out + 1024) : (float*)0);
        gru_kernel<<<1, 512>>>(sp, gwih, gwhh, gbih, gbhh, rlg, rlb,
                               rw1, rb1, rw2, rb2, (it == 2) ? out : (float*)0);
    }
}

// round 7
// speedup vs baseline: 1.7042x; 1.2193x over previous
#include <cuda_runtime.h>
#include <cuda_bf16.h>
#include <math.h>
#include <stdint.h>

// ---------------- problem constants ----------------
#define N3   405224   // 74^3

typedef unsigned long long ull;

// ---------------- f32x2 packed helpers (lnkv) ----------------
__device__ __forceinline__ ull pk(float lo, float hi) {
    ull r; asm("mov.b64 %0, {%1,%2};" : "=l"(r) : "f"(lo), "f"(hi)); return r;
}
__device__ __forceinline__ float2 unpk(ull p) {
    float2 f; asm("mov.b64 {%0,%1}, %2;" : "=f"(f.x), "=f"(f.y) : "l"(p)); return f;
}
__device__ __forceinline__ void fma2(ull& d, ull a, ull b, ull c) {
    asm("fma.rn.f32x2 %0, %1, %2, %3;" : "=l"(d) : "l"(a), "l"(b), "l"(c));
}
__device__ __forceinline__ uint32_t smem_u32(const void* p) {
    uint32_t a;
    asm("{ .reg .u64 t; cvta.to.shared.u64 t, %1; cvt.u32.u64 %0, t; }" : "=r"(a) : "l"(p));
    return a;
}
__device__ __forceinline__ void ldsm4(uint32_t& r0, uint32_t& r1, uint32_t& r2, uint32_t& r3,
                                      uint32_t addr) {
    asm volatile("ldmatrix.sync.aligned.m8n8.x4.shared.b16 {%0,%1,%2,%3}, [%4];"
                 : "=r"(r0), "=r"(r1), "=r"(r2), "=r"(r3) : "r"(addr));
}

// ---------------- device scratch ----------------
__device__ float g_buf1[2 * 32 * 78 * 78 * 78];   // conv1 out / conv3 out
__device__ float g_buf2[2 * 32 * 76 * 76 * 76];   // conv2 out
__device__ float g_k[2 * 64 * N3];
__device__ float g_v[2 * 64 * N3];
__device__ float g_slots[1024];
__device__ float g_q[1024];
__device__ float g_upd[1024];
__device__ float g_rowsum[16];
__device__ __nv_bfloat16 g_B2p[27 * 32 * 64];     // [tap][cout][hi32|lo32]
__device__ __nv_bfloat16 g_B3p[27 * 32 * 64];

// =====================================================================
// Weight prep: w[cout][cin][27] fp32 -> [tap][cout][hi(32)|lo(32)] bf16
// =====================================================================
__global__ void prepB_kernel(const float* __restrict__ w, __nv_bfloat16* __restrict__ Bg) {
    int idx = blockIdx.x * 256 + threadIdx.x;   // 0..27647
    if (idx >= 27648) return;
    int t = idx >> 10;
    int r = idx & 1023;
    int n = r >> 5;
    int ci = r & 31;
    float x = w[(n * 32 + ci) * 27 + t];
    __nv_bfloat16 hi = __float2bfloat16(x);
    float rem = x - __bfloat162float(hi);
    __nv_bfloat16 lo = __float2bfloat16(rem);
    Bg[(t * 32 + n) * 64 + ci] = hi;
    Bg[(t * 32 + n) * 64 + 32 + ci] = lo;
}

// =====================================================================
// mma.sync bf16 split-2 implicit-GEMM conv3d, 32ci->32co, relu.
// 512 threads / 16 warps (4 per SMSP); warp = 16 tokens x 32 cout.
// ldmatrix.x4 fragment feeds; product-major MMA issue.
// =====================================================================
#define BROW_W 36
#define BROW_B (BROW_W * 4)
#define B_BYTES (27 * 32 * BROW_B)         // 124416
#define PROW_W 36
#define PROW_B (PROW_W * 4)
#define P_OFF  B_BYTES
#define P_BYTES (600 * PROW_B)             // 86400
#define SMEM_MMA (P_OFF + P_BYTES)         // 210816

#define MMA_BF16(d, a, b)                                                  \
    asm volatile("mma.sync.aligned.m16n8k16.row.col.f32.bf16.bf16.f32 "    \
                 "{%0,%1,%2,%3}, {%4,%5,%6,%7}, {%8,%9}, {%0,%1,%2,%3};"   \
                 : "+f"(d[0]), "+f"(d[1]), "+f"(d[2]), "+f"(d[3])          \
                 : "r"(a[0]), "r"(a[1]), "r"(a[2]), "r"(a[3]),             \
                   "r"(b[0]), "r"(b[1]))

__global__ __launch_bounds__(512)
void conv_mma_kernel(const float* __restrict__ in, const __nv_bfloat16* __restrict__ Bg,
                     const float* __restrict__ bias, float* __restrict__ out, int Di) {
    const int Do = Di - 2;
    extern __shared__ char smem[];
    __shared__ float s_bias[32];
    const int tid  = threadIdx.x;
    const int wid  = tid >> 5;        // 0..15
    const int lane = tid & 31;
    const int grp  = lane >> 2;
    const int tig  = lane & 3;

    // copy B into smem with row padding (32 -> 36 words)
    {
        const uint32_t* src = (const uint32_t*)Bg;
        uint32_t* dst = (uint32_t*)smem;
        for (int i = tid; i < 27648; i += 512) {
            int row = i >> 5, w = i & 31;
            dst[row * BROW_W + w] = src[i];
        }
    }
    if (tid < 32) s_bias[tid] = bias[tid];
    __syncthreads();

    char* patch = smem + P_OFF;
    const uint32_t patch_u = smem_u32(patch);
    const uint32_t bsm_u   = smem_u32(smem);

    // ---- per-lane LDSM base addresses ----
    // A: row = token (wid*16 + (lane&15)), kblock = lane>>4
    const int tokA = wid * 16 + (lane & 15);
    const int dA = tokA >> 6, hA = (tokA >> 3) & 7, wA = tokA & 7;
    const uint32_t aBase = patch_u + (uint32_t)(dA * 100 + hA * 10 + wA) * PROW_B + (lane >> 4) * 16;
    // B: pair p covers nt=2p,2p+1. cout = p*16 + (lane>>4)*8 + (lane&7), kb=(lane>>3)&1
    uint32_t bBase[2];
#pragma unroll
    for (int p = 0; p < 2; p++)
        bBase[p] = bsm_u + (uint32_t)(p * 16 + ((lane >> 4) << 3) + (lane & 7)) * BROW_B +
                   ((lane >> 3) & 1) * 16;

    // epilogue tokens: rows grp and grp+8 of this warp's 16-token tile
    const int tok0 = wid * 16 + grp;
    const int tok1 = tok0 + 8;

    // patch-fill slots (<=2 per thread at 512 threads)
    int pd_[2], ph_[2], pw_[2], pofs_[2];
    bool sv_[2];
#pragma unroll
    for (int q = 0; q < 2; q++) {
        int s = tid + 512 * q;
        sv_[q] = (s < 600);
        int ss = sv_[q] ? s : 0;
        pd_[q] = ss / 100; int r2 = ss - pd_[q] * 100;
        ph_[q] = r2 / 10;  pw_[q] = r2 - ph_[q] * 10;
        pofs_[q] = ss * PROW_B;
    }

    const int nd = (Do + 3) >> 2, nhw = (Do + 7) >> 3;
    const int ntb = nd * nhw * nhw;
    const int DiDi = Di * Di;

    for (int ti = blockIdx.x; ti < 2 * ntb; ti += gridDim.x) {
        const int b = ti / ntb;
        int r = ti - b * ntb;
        const int td = r / (nhw * nhw); r -= td * (nhw * nhw);
        const int th = r / nhw, tw = r - (r / nhw) * nhw;
        const int d0 = td * 4, h0 = th * 8, w0 = tw * 8;

        __syncthreads();   // previous tile's reads done
        // ---- patch fill ----
#pragma unroll
        for (int q = 0; q < 2; q++) {
            if (!sv_[q]) continue;
            const int gd = d0 + pd_[q], gh = h0 + ph_[q], gw = w0 + pw_[q];
            const bool ok = (gd < Di) & (gh < Di) & (gw < Di);
            const float* src = in + (size_t)b * 32 * Di * DiDi + (size_t)(gd * Di + gh) * Di + gw;
            char* pdst = patch + pofs_[q];
#pragma unroll 4
            for (int ci = 0; ci < 32; ci++) {
                float x = ok ? src[(size_t)ci * Di * DiDi] : 0.f;
                __nv_bfloat16 hi = __float2bfloat16(x);
                float rem = x - __bfloat162float(hi);
                __nv_bfloat16 lo = __float2bfloat16(rem);
                *(__nv_bfloat16*)(pdst + ci * 2) = hi;
                *(__nv_bfloat16*)(pdst + 64 + ci * 2) = lo;
            }
        }
        __syncthreads();

        float acc[4][4];
#pragma unroll
        for (int nt = 0; nt < 4; nt++)
#pragma unroll
            for (int q = 0; q < 4; q++) acc[nt][q] = 0.f;

#pragma unroll 1
        for (int t = 0; t < 27; t++) {
            const int kd = t / 9; const int r9 = t - kd * 9;
            const int kh = r9 / 3; const int kw = r9 - kh * 3;
            const uint32_t aTap = aBase + (uint32_t)(kd * 100 + kh * 10 + kw) * PROW_B;
            const uint32_t bTap = (uint32_t)t * 32 * BROW_B;

            uint32_t af[2][2][4];   // [ks][sp][4]
            uint32_t bf[2][4][2][2];// [ks][nt][sp][2]
#pragma unroll
            for (int ks = 0; ks < 2; ks++) {
#pragma unroll
                for (int sp = 0; sp < 2; sp++)
                    ldsm4(af[ks][sp][0], af[ks][sp][1], af[ks][sp][2], af[ks][sp][3],
                          aTap + ks * 32 + sp * 64);
#pragma unroll
                for (int p = 0; p < 2; p++)
#pragma unroll
                    for (int sp = 0; sp < 2; sp++) {
                        uint32_t r0, r1, r2, r3;
                        ldsm4(r0, r1, r2, r3, bBase[p] + bTap + ks * 32 + sp * 64);
                        bf[ks][2 * p][sp][0] = r0;  bf[ks][2 * p][sp][1] = r1;
                        bf[ks][2 * p + 1][sp][0] = r2;  bf[ks][2 * p + 1][sp][1] = r3;
                    }
            }
            // product-major: same accumulator revisited after 4 independent MMAs
#pragma unroll
            for (int ks = 0; ks < 2; ks++)
#pragma unroll
                for (int nt = 0; nt < 4; nt++)
                    MMA_BF16(acc[nt], af[ks][0], bf[ks][nt][0]);   // hi*hi
#pragma unroll
            for (int ks = 0; ks < 2; ks++)
#pragma unroll
                for (int nt = 0; nt < 4; nt++)
                    MMA_BF16(acc[nt], af[ks][1], bf[ks][nt][0]);   // lo*hi
#pragma unroll
            for (int ks = 0; ks < 2; ks++)
#pragma unroll
                for (int nt = 0; nt < 4; nt++)
                    MMA_BF16(acc[nt], af[ks][0], bf[ks][nt][1]);   // hi*lo
        }

        // ---- epilogue: bias + relu + predicated store ----
#pragma unroll
        for (int nt = 0; nt < 4; nt++)
#pragma unroll
            for (int q = 0; q < 4; q++) {
                int t = (q >> 1) ? tok1 : tok0;
                int c = nt * 8 + tig * 2 + (q & 1);
                int dd = t >> 6, hh = (t >> 3) & 7, ww = t & 7;
                int od = d0 + dd, oh = h0 + hh, ow = w0 + ww;
                if (od < Do && oh < Do && ow < Do) {
                    float v = acc[nt][q] + s_bias[c];
                    out[(((size_t)(b * 32 + c) * Do + od) * Do + oh) * Do + ow] =
                        v > 0.f ? v : 0.f;
                }
            }
    }
}

// =====================================================================
// Scalar conv for conv1 (CIN=4).
// =====================================================================
template <int CIN>
__global__ __launch_bounds__(256)
void conv3d_kernel(const float* __restrict__ in, const float* __restrict__ wg,
                   const float* __restrict__ bias, float* __restrict__ out,
                   int Di) {
    const int Do = Di - 2;
    const int tid = threadIdx.x;
    const int b  = blockIdx.z;
    const int nW = (Do + 7) >> 3;
    const int h0 = (blockIdx.x / nW) * 8;
    const int w0 = (blockIdx.x % nW) * 8;
    const int d0 = blockIdx.y * 4;

    extern __shared__ float smemf[];
    float* ws    = smemf;
    float* patch = smemf + CIN * 27 * 32;

    const int WTOT = 32 * CIN * 27;
    for (int idx = tid; idx < WTOT; idx += 256) {
        int co = idx / (CIN * 27);
        int r  = idx - co * (CIN * 27);
        ws[r * 32 + co] = wg[idx];
    }
    for (int idx = tid; idx < CIN * 600; idx += 256) {
        int ci = idx / 600;
        int r  = idx - ci * 600;
        int dd = r / 100;  int r2 = r - dd * 100;
        int hh = r2 / 10;  int ww = r2 - hh * 10;
        int gd = d0 + dd, gh = h0 + hh, gw = w0 + ww;
        float val = 0.f;
        if (gd < Di && gh < Di && gw < Di)
            val = in[(((b * CIN + ci) * Di + gd) * Di + gh) * Di + gw];
        patch[idx] = val;
    }
    __syncthreads();

    const int cout = tid >> 3;
    const int hg   = tid & 7;
    const float bv = bias[cout];

    float acc[4][8];
#pragma unroll
    for (int i = 0; i < 4; i++)
#pragma unroll
        for (int j = 0; j < 8; j++) acc[i][j] = 0.f;

    for (int ci = 0; ci < CIN; ci++) {
        float wr[27];
#pragma unroll
        for (int t = 0; t < 27; t++) wr[t] = ws[(ci * 27 + t) * 32 + cout];
        const float* pbase = patch + ci * 600;
#pragma unroll
        for (int kh = 0; kh < 3; kh++) {
            const float* rowb = pbase + (hg + kh) * 10;
#pragma unroll
            for (int dd = 0; dd < 6; dd++) {
                float row[10];
                const float2* rp = (const float2*)(rowb + dd * 100);
#pragma unroll
                for (int j = 0; j < 5; j++) ((float2*)row)[j] = rp[j];
#pragma unroll
                for (int kd = 0; kd < 3; kd++) {
                    const int dlo = dd - kd;
                    if (dlo >= 0 && dlo < 4) {
#pragma unroll
                        for (int kw = 0; kw < 3; kw++) {
                            float wv = wr[kd * 9 + kh * 3 + kw];
#pragma unroll
                            for (int w = 0; w < 8; w++)
                                acc[dlo][w] += wv * row[w + kw];
                        }
                    }
                }
            }
        }
    }
    __syncthreads();
#pragma unroll
    for (int dd = 0; dd < 4; dd++)
#pragma unroll
        for (int w = 0; w < 8; w++) {
            float v = acc[dd][w] + bv;
            patch[cout * 256 + dd * 64 + hg * 8 + w] = v > 0.f ? v : 0.f;
        }
    __syncthreads();
    const int DoDo = Do * Do;
    for (int idx = tid; idx < 8192; idx += 256) {
        int co = idx >> 8;
        int r  = idx & 255;
        int dd = r >> 6;
        int hh = (r >> 3) & 7;
        int w  = r & 7;
        int od = d0 + dd, oh = h0 + hh, ow = w0 + w;
        if (od < Do && oh < Do && ow < Do)
            out[((b * 32 + co) * Do + od) * DoDo + oh * Do + ow] = patch[idx];
    }
}

// =====================================================================
// feature LN + k/v projection
// =====================================================================
__global__ __launch_bounds__(256)
void lnkv_kernel(const float* __restrict__ x, const float* __restrict__ lg,
                 const float* __restrict__ lb, const float* __restrict__ kw,
                 const float* __restrict__ vw) {
    __shared__ float kws[2048], vws[2048], gs[32], bs[32];
    const int tid = threadIdx.x;
    for (int i = tid; i < 2048; i += 256) { kws[i] = kw[i]; vws[i] = vw[i]; }
    if (tid < 32) { gs[tid] = lg[tid]; bs[tid] = lb[tid]; }
    __syncthreads();
    const int b = blockIdx.y;
    const int j = blockIdx.x * 256 + tid;
    if (j >= N3) return;
    float xv[32];
    float s = 0.f;
#pragma unroll
    for (int c = 0; c < 32; c++) { xv[c] = x[(b * 32 + c) * N3 + j]; s += xv[c]; }
    const float m = s * (1.f / 32.f);
    float vs = 0.f;
#pragma unroll
    for (int c = 0; c < 32; c++) { float d = xv[c] - m; vs += d * d; }
    const float inv = rsqrtf(vs * (1.f / 32.f) + 1e-5f);
    ull xp[16];
#pragma unroll
    for (int c2 = 0; c2 < 16; c2++) {
        float a0 = (xv[2 * c2] - m) * inv * gs[2 * c2] + bs[2 * c2];
        float a1 = (xv[2 * c2 + 1] - m) * inv * gs[2 * c2 + 1] + bs[2 * c2 + 1];
        xp[c2] = pk(a0, a1);
    }
#pragma unroll 4
    for (int d = 0; d < 64; d++) {
        const ull* k8 = (const ull*)(kws + d * 32);
        const ull* v8 = (const ull*)(vws + d * 32);
        ull ka = 0ull, va = 0ull;
#pragma unroll
        for (int c2 = 0; c2 < 16; c2++) {
            fma2(ka, xp[c2], k8[c2], ka);
            fma2(va, xp[c2], v8[c2], va);
        }
        float2 kp = unpk(ka), vp = unpk(va);
        g_k[(b * 64 + d) * N3 + j] = kp.x + kp.y;
        g_v[(b * 64 + d) * N3 + j] = vp.x + vp.y;
    }
}

// =====================================================================
// q projection
// =====================================================================
__global__ __launch_bounds__(256)
void q_kernel(const float* __restrict__ slots, const float* __restrict__ lg,
              const float* __restrict__ lb, const float* __restrict__ qw) {
    __shared__ float s[1024], qws[4096], gs[64], bs[64], mm[16], iv[16];
    const int tid = threadIdx.x;
    for (int i = tid; i < 1024; i += 256) { s[i] = slots[i]; g_upd[i] = 0.f; }
    for (int i = tid; i < 4096; i += 256) qws[i] = qw[i];
    if (tid < 64) { gs[tid] = lg[tid]; bs[tid] = lb[tid]; }
    if (tid < 16) g_rowsum[tid] = 0.f;
    __syncthreads();
    if (tid < 16) {
        float sum = 0.f;
        for (int d = 0; d < 64; d++) sum += s[tid * 64 + d];
        float m = sum * (1.f / 64.f);
        float vs = 0.f;
        for (int d = 0; d < 64; d++) { float t = s[tid * 64 + d] - m; vs += t * t; }
        mm[tid] = m;
        iv[tid] = rsqrtf(vs * (1.f / 64.f) + 1e-5f);
    }
    __syncthreads();
    for (int k = 0; k < 4; k++) {
        int o = k * 256 + tid;
        int r = o >> 6, d = o & 63;
        float m = mm[r], inv = iv[r];
        float acc = 0.f;
#pragma unroll
        for (int c = 0; c < 64; c++)
            acc += ((s[r * 64 + c] - m) * inv * gs[c] + bs[c]) * qws[d * 64 + c];
        g_q[o] = acc * 0.125f;
    }
}

// =====================================================================
// fused attention iteration
// =====================================================================
__global__ __launch_bounds__(256)
void attn_kernel(float* __restrict__ attn_out) {
    extern __shared__ float sm[];
    float* qs = sm;
    float* as = sm + 512;
    float* vs = sm + 2560;
    const int tid  = threadIdx.x;
    const int b    = blockIdx.y;
    const int dd   = tid & 63;
    const int ib   = tid >> 6;
    const int wid  = tid >> 5;
    const int lane = tid & 31;
    for (int i = tid; i < 512; i += 256) qs[i] = g_q[b * 512 + i];

    float acc0 = 0.f, acc1 = 0.f, rs = 0.f;
    const int nch = (N3 + 255) >> 8;
    for (int c = blockIdx.x; c < nch; c += gridDim.x) {
        const int j0 = c << 8;
        const int j  = j0 + tid;
        __syncthreads();
        float a[8];
        if (j < N3) {
            float dots[8];
#pragma unroll
            for (int i = 0; i < 8; i++) dots[i] = 0.f;
#pragma unroll 16
            for (int d = 0; d < 64; d++) {
                float kv = g_k[(b * 64 + d) * N3 + j];
#pragma unroll
                for (int i = 0; i < 8; i++) dots[i] += qs[i * 64 + d] * kv;
            }
            float mx = dots[0];
#pragma unroll
            for (int i = 1; i < 8; i++) mx = fmaxf(mx, dots[i]);
            float ssum = 0.f;
#pragma unroll
            for (int i = 0; i < 8; i++) { a[i] = expf(dots[i] - mx); ssum += a[i]; }
            const float rinv = 1.f / ssum;
#pragma unroll
            for (int i = 0; i < 8; i++) a[i] = a[i] * rinv + 1e-8f;
            if (attn_out) {
#pragma unroll
                for (int i = 0; i < 8; i++)
                    attn_out[(b * 8 + i) * N3 + j] = a[i];
            }
        } else {
#pragma unroll
            for (int i = 0; i < 8; i++) a[i] = 0.f;
        }
#pragma unroll
        for (int i = 0; i < 8; i++) as[i * 256 + tid] = a[i];
        for (int idx = tid; idx < 64 * 256; idx += 256) {
            int d  = idx >> 8, jj = idx & 255;
            int jg = j0 + jj;
            vs[d * 257 + jj] = (jg < N3) ? g_v[(b * 64 + d) * N3 + jg] : 0.f;
        }
        __syncthreads();
        {
            float p = 0.f;
#pragma unroll
            for (int k = 0; k < 8; k++) p += as[wid * 256 + lane + k * 32];
#pragma unroll
            for (int off = 16; off; off >>= 1) p += __shfl_xor_sync(0xffffffffu, p, off);
            rs += p;
        }
        const float* ap0 = as + ib * 256;
        const float* ap1 = as + (ib + 4) * 256;
        const float* vp  = vs + dd * 257;
#pragma unroll 8
        for (int jj = 0; jj < 256; jj++) {
            float vv = vp[jj];
            acc0 += ap0[jj] * vv;
            acc1 += ap1[jj] * vv;
        }
    }
    atomicAdd(&g_upd[(b * 8 + ib) * 64 + dd], acc0);
    atomicAdd(&g_upd[(b * 8 + ib + 4) * 64 + dd], acc1);
    if (lane == 0) atomicAdd(&g_rowsum[b * 8 + wid], rs);
}

// =====================================================================
// GRU cell + LN + MLP residual
// =====================================================================
__global__ __launch_bounds__(512)
void gru_kernel(const float* __restrict__ slots_prev,
                const float* __restrict__ wih, const float* __restrict__ whh,
                const float* __restrict__ bih, const float* __restrict__ bhh,
                const float* __restrict__ lng, const float* __restrict__ lnb,
                const float* __restrict__ w1, const float* __restrict__ rb1,
                const float* __restrict__ w2, const float* __restrict__ rb2,
                float* __restrict__ slots_final) {
    __shared__ float S[9216];
    float* u  = S;
    float* h  = S + 1024;
    float* xg = S + 2048;
    float* hg = S + 5120;
    float* nh = S + 8192;
    float* normed = S + 2048;
    float* t1     = S + 5120;
    const int tid = threadIdx.x;

    for (int k = 0; k < 2; k++) {
        int idx = k * 512 + tid;
        int r = idx >> 6;
        u[idx] = g_upd[idx] / g_rowsum[r];
        h[idx] = slots_prev[idx];
    }
    __syncthreads();
    for (int k = 0; k < 6; k++) {
        int p = k * 512 + tid;
        int r = p / 192, c = p - r * 192;
        float xa = bih[c], ha = bhh[c];
        const float* wr = wih + c * 64;
        const float* hr = whh + c * 64;
#pragma unroll 16
        for (int d = 0; d < 64; d++) {
            xa += u[r * 64 + d] * wr[d];
            ha += h[r * 64 + d] * hr[d];
        }
        xg[p] = xa; hg[p] = ha;
    }
    __syncthreads();
    for (int k = 0; k < 2; k++) {
        int idx = k * 512 + tid;
        int r = idx >> 6, d = idx & 63;
        float rg = 1.f / (1.f + expf(-(xg[r * 192 + d] + hg[r * 192 + d])));
        float z  = 1.f / (1.f + expf(-(xg[r * 192 + 64 + d] + hg[r * 192 + 64 + d])));
        float n  = tanhf(xg[r * 192 + 128 + d] + rg * hg[r * 192 + 128 + d]);
        nh[idx] = (1.f - z) * n + z * h[idx];
    }
    __syncthreads();
    {
        const int w = tid >> 5, lane = tid & 31;
        float e0 = nh[w * 64 + lane], e1 = nh[w * 64 + 32 + lane];
        float s = e0 + e1;
#pragma unroll
        for (int off = 16; off; off >>= 1) s += __shfl_xor_sync(0xffffffffu, s, off);
        float m = s * (1.f / 64.f);
        float d0 = e0 - m, d1 = e1 - m;
        float vq = d0 * d0 + d1 * d1;
#pragma unroll
        for (int off = 16; off; off >>= 1) vq += __shfl_xor_sync(0xffffffffu, vq, off);
        float inv = rsqrtf(vq * (1.f / 64.f) + 1e-5f);
        normed[w * 64 + lane]      = d0 * inv * lng[lane] + lnb[lane];
        normed[w * 64 + 32 + lane] = d1 * inv * lng[32 + lane] + lnb[32 + lane];
    }
    __syncthreads();
    for (int k = 0; k < 4; k++) {
        int p = k * 512 + tid;
        int r = p >> 7, c = p & 127;
        float acc = rb1[c];
        const float* wr = w1 + c * 64;
#pragma unroll 16
        for (int d = 0; d < 64; d++) acc += normed[r * 64 + d] * wr[d];
        t1[p] = fmaxf(acc, 0.f);
    }
    __syncthreads();
    for (int k = 0; k < 2; k++) {
        int idx = k * 512 + tid;
        int r = idx >> 6, d = idx & 63;
        float acc = rb2[d];
        const float* wr = w2 + d * 128;
#pragma unroll 16
        for (int c = 0; c < 128; c++) acc += t1[r * 128 + c] * wr[c];
        float val = nh[idx] + acc;
        g_slots[idx] = val;
        if (slots_final) slots_final[idx] = val;
    }
}

// =====================================================================
// host driver
// =====================================================================
extern "C" void kernel_launch(void* const* d_in, const int* in_sizes, int n_in,
                              void* d_out, int out_size) {
    (void)in_sizes; (void)n_in; (void)out_size;
    const float* p_slots = (const float*)d_in[0];
    const float* p_oin   = (const float*)d_in[1];
    const float* w1  = (const float*)d_in[2];
    const float* b1  = (const float*)d_in[3];
    const float* w2  = (const float*)d_in[4];
    const float* b2  = (const float*)d_in[5];
    const float* w3  = (const float*)d_in[6];
    const float* b3  = (const float*)d_in[7];
    const float* kw  = (const float*)d_in[8];
    const float* vw  = (const float*)d_in[9];
    const float* qlg = (const float*)d_in[10];
    const float* qlb = (const float*)d_in[11];
    const float* qw  = (const float*)d_in[12];
    const float* gwih = (const float*)d_in[13];
    const float* gwhh = (const float*)d_in[14];
    const float* gbih = (const float*)d_in[15];
    const float* gbhh = (const float*)d_in[16];
    const float* rlg = (const float*)d_in[17];
    const float* rlb = (const float*)d_in[18];
    const float* rw1 = (const float*)d_in[19];
    const float* rb1 = (const float*)d_in[20];
    const float* rw2 = (const float*)d_in[21];
    const float* rb2 = (const float*)d_in[22];
    const float* flg = (const float*)d_in[23];
    const float* flb = (const float*)d_in[24];
    float* out = (float*)d_out;

    const size_t smem4  = (size_t)(4 * 27 * 32 + 8192) * sizeof(float);
    const size_t smemA  = (size_t)(512 + 2048 + 64 * 257) * sizeof(float);
    cudaFuncSetAttribute(conv3d_kernel<4>, cudaFuncAttributeMaxDynamicSharedMemorySize, (int)smem4);
    cudaFuncSetAttribute(conv_mma_kernel, cudaFuncAttributeMaxDynamicSharedMemorySize, SMEM_MMA);
    cudaFuncSetAttribute(attn_kernel, cudaFuncAttributeMaxDynamicSharedMemorySize, (int)smemA);

    float *buf1, *buf2, *slots_g;
    __nv_bfloat16 *B2p, *B3p;
    cudaGetSymbolAddress((void**)&buf1, g_buf1);
    cudaGetSymbolAddress((void**)&buf2, g_buf2);
    cudaGetSymbolAddress((void**)&slots_g, g_slots);
    cudaGetSymbolAddress((void**)&B2p, g_B2p);
    cudaGetSymbolAddress((void**)&B3p, g_B3p);

    // weight prep for tensor-core convs
    prepB_kernel<<<108, 256>>>(w2, B2p);
    prepB_kernel<<<108, 256>>>(w3, B3p);

    // conv1: 80 -> 78 (scalar, CIN=4)
    conv3d_kernel<4><<<dim3(10 * 10, 20, 2), 256, smem4>>>(p_oin, w1, b1, buf1, 80);
    // conv2: 78 -> 76 (mma.sync)
    conv_mma_kernel<<<148, 512, SMEM_MMA>>>(buf1, B2p, b2, buf2, 78);
    // conv3: 76 -> 74 (mma.sync)
    conv_mma_kernel<<<148, 512, SMEM_MMA>>>(buf2, B3p, b3, buf1, 76);
    // feature LN + k/v projection
    lnkv_kernel<<<dim3((N3 + 255) / 256, 2), 256>>>(buf1, flg, flb, kw, vw);

    for (int it = 0; it < 3; it++) {
        const float* sp = (it == 0) ? p_slots : slots_g;
        q_kernel<<<1, 256>>>(sp, qlg, qlb, qw);
        attn_kernel<<<dim3(222, 2), 256, smemA>>>((it == 2) ? (out + 1024) : (float*)0);
        gru_kernel<<<1, 512>>>(sp, gwih, gwhh, gbih, gbhh, rlg, rlb,
                               rw1, rb1, rw2, rb2, (it == 2) ? out : (float*)0);
    }
}